// round 7
// baseline (speedup 1.0000x reference)
#include <cuda_runtime.h>
#include <cstdint>

#define N_NODES 20000
#define N_EDGES 100000
#define DN 256
#define DE 256
#define DH 512
#define NLAYERS 2

// ---------------- scratch (device globals: allocation-free) ----------------
__device__ float g_m1 [(size_t)N_EDGES * DH];   // relu(concat @ W1a + b1a)
__device__ float g_e  [(size_t)N_EDGES * DE];   // edge features between layers
__device__ float g_x  [(size_t)N_NODES * DN];   // node features between layers
__device__ float g_agg[(size_t)N_NODES * DH];   // segment-sum accumulator
__device__ float g_h  [(size_t)N_NODES * DH];   // relu(agg_norm @ W2a + b2a)
__device__ float g_cnt[N_NODES];                // in-degree counts

typedef unsigned long long u64;

// ---------------- packed f32x2 helpers (SASS FFMA2 path) ----------------
__device__ __forceinline__ u64 pack2(float lo, float hi) {
    u64 r;
    asm("mov.b64 %0, {%1, %2};" : "=l"(r) : "f"(lo), "f"(hi));
    return r;
}
__device__ __forceinline__ float2 unpack2(u64 v) {
    float2 r;
    asm("mov.b64 {%0, %1}, %2;" : "=f"(r.x), "=f"(r.y) : "l"(v));
    return r;
}
__device__ __forceinline__ void ffma2(u64& d, u64 a, u64 b) {
    asm("fma.rn.f32x2 %0, %1, %2, %0;" : "+l"(d) : "l"(a), "l"(b));
}

// Inner product body over one BK=16 shared tile.
// acc[i][j2] packs output cols (2*j2, 2*j2+1); B pairs come free from LDS.128.
#define MM_BODY()                                                          \
    _Pragma("unroll")                                                      \
    for (int kk = 0; kk < 16; ++kk) {                                      \
        float4 a0 = *(const float4*)&As[kk][tm * 8];                       \
        float4 a1 = *(const float4*)&As[kk][tm * 8 + 4];                   \
        ulonglong2 b01 = *(const ulonglong2*)&Bs[kk][tn * 8];              \
        ulonglong2 b23 = *(const ulonglong2*)&Bs[kk][tn * 8 + 4];          \
        u64 bb0 = b01.x, bb1 = b01.y, bb2 = b23.x, bb3 = b23.y;            \
        float av[8] = {a0.x, a0.y, a0.z, a0.w, a1.x, a1.y, a1.z, a1.w};    \
        _Pragma("unroll")                                                  \
        for (int i = 0; i < 8; ++i) {                                      \
            u64 ar = pack2(av[i], av[i]);                                  \
            ffma2(acc[i][0], ar, bb0);                                     \
            ffma2(acc[i][1], ar, bb1);                                     \
            ffma2(acc[i][2], ar, bb2);                                     \
            ffma2(acc[i][3], ar, bb3);                                     \
        }                                                                  \
    }

#define ZERO_ACC()                                                         \
    u64 acc[8][4];                                                         \
    _Pragma("unroll")                                                      \
    for (int i = 0; i < 8; ++i)                                            \
        _Pragma("unroll")                                                  \
        for (int j = 0; j < 4; ++j) acc[i][j] = 0ull;

#define UNPACK_RELU(o, i, bset)                                            \
    float o[8];                                                            \
    _Pragma("unroll")                                                      \
    for (int j2 = 0; j2 < 4; ++j2) {                                       \
        float2 v = unpack2(acc[i][j2]);                                    \
        o[2 * j2]     = fmaxf(v.x + bset[2 * j2], 0.f);                    \
        o[2 * j2 + 1] = fmaxf(v.y + bset[2 * j2 + 1], 0.f);                \
    }

// ---------------- small utility kernels ----------------
__global__ void zero_cnt_kernel() {
    int i = blockIdx.x * blockDim.x + threadIdx.x;
    if (i < N_NODES) g_cnt[i] = 0.f;
}
__global__ void zero_agg_kernel() {
    int i = blockIdx.x * blockDim.x + threadIdx.x;
    if (i < N_NODES * DH / 4)
        ((float4*)g_agg)[i] = make_float4(0.f, 0.f, 0.f, 0.f);
}
__global__ void count_kernel(const int* __restrict__ dstI) {
    int e = blockIdx.x * blockDim.x + threadIdx.x;
    if (e < N_EDGES) atomicAdd(&g_cnt[dstI[e]], 1.f);
}

// ============================================================================
// GEMM1: m1 = relu([x[dst] | e | x[src]] @ W1a + b1a)   (E x 768)@(768 x 512)
// A rows are gathered on the fly. Grid: (4 N-tiles, 782 M-tiles).
// ============================================================================
__global__ void __launch_bounds__(256, 2) gemm1_kernel(
    const float* __restrict__ xin, const float* __restrict__ ein,
    const int* __restrict__ srcI, const int* __restrict__ dstI,
    const float* __restrict__ W, const float* __restrict__ bias)
{
    __shared__ float As[16][128];
    __shared__ float Bs[16][128];
    __shared__ int sDst[128], sSrc[128];

    const int tid = threadIdx.x;
    const int n0 = blockIdx.x * 128;
    const int m0 = blockIdx.y * 128;
    const int tm = tid >> 4, tn = tid & 15;

    if (tid < 128) {
        int r = m0 + tid;
        sDst[tid] = (r < N_EDGES) ? dstI[r] : 0;
        sSrc[tid] = (r < N_EDGES) ? srcI[r] : 0;
    }
    __syncthreads();

    ZERO_ACC();

    const int am = tid >> 2, ak = (tid & 3) << 2;
    const int bk = tid >> 4, bn = (tid & 15) << 2;

    for (int k0 = 0; k0 < 2 * DN + DE; k0 += 16) {
#pragma unroll
        for (int h = 0; h < 2; ++h) {
            int lm = am + h * 64;
            int r = m0 + lm;
            float4 v = make_float4(0.f, 0.f, 0.f, 0.f);
            if (r < N_EDGES) {
                int kg = k0 + ak;
                const float* p;
                if (kg < DN)            p = xin + (size_t)sDst[lm] * DN + kg;
                else if (kg < DN + DE)  p = ein + (size_t)r * DE + (kg - DN);
                else                    p = xin + (size_t)sSrc[lm] * DN + (kg - DN - DE);
                v = *(const float4*)p;
            }
            As[ak + 0][lm] = v.x; As[ak + 1][lm] = v.y;
            As[ak + 2][lm] = v.z; As[ak + 3][lm] = v.w;
        }
        {
            const float* wp = W + (size_t)(k0 + bk) * DH + n0;
            *(float4*)&Bs[bk][bn]      = *(const float4*)(wp + bn);
            *(float4*)&Bs[bk][bn + 64] = *(const float4*)(wp + bn + 64);
        }
        __syncthreads();
        MM_BODY();
        __syncthreads();
    }

    float bset[8];
    {
        float4 b0 = *(const float4*)(bias + n0 + tn * 8);
        float4 b1 = *(const float4*)(bias + n0 + tn * 8 + 4);
        bset[0] = b0.x; bset[1] = b0.y; bset[2] = b0.z; bset[3] = b0.w;
        bset[4] = b1.x; bset[5] = b1.y; bset[6] = b1.z; bset[7] = b1.w;
    }
#pragma unroll
    for (int i = 0; i < 8; ++i) {
        int r = m0 + tm * 8 + i;
        if (r >= N_EDGES) continue;
        UNPACK_RELU(o, i, bset);
        float* op = g_m1 + (size_t)r * DH + n0 + tn * 8;
        *(float4*)op       = make_float4(o[0], o[1], o[2], o[3]);
        *(float4*)(op + 4) = make_float4(o[4], o[5], o[6], o[7]);
    }
}

// ============================================================================
// GEMM2: m2 = relu(m1 @ W1b + b1b)   (E x 512)@(512 x 1280)
// Epilogue by column region: [0,512)+[768,1280) -> atomicAdd into g_agg[dst]
// (sum of the two relu branches == xm, order-free); [512,768) -> new_e.
// Grid: (10 N-tiles, 782 M-tiles).
// ============================================================================
__global__ void __launch_bounds__(256, 2) gemm2_kernel(
    const int* __restrict__ dstI,
    const float* __restrict__ W, const float* __restrict__ bias,
    float* __restrict__ eout)
{
    __shared__ float As[16][128];
    __shared__ float Bs[16][128];
    __shared__ int sDst[128];

    const int tid = threadIdx.x;
    const int n0 = blockIdx.x * 128;
    const int m0 = blockIdx.y * 128;
    const int tm = tid >> 4, tn = tid & 15;
    const int ldW = 2 * DH + DE;  // 1280

    if (tid < 128) {
        int r = m0 + tid;
        sDst[tid] = (r < N_EDGES) ? dstI[r] : 0;
    }
    __syncthreads();

    ZERO_ACC();

    const int am = tid >> 2, ak = (tid & 3) << 2;
    const int bk = tid >> 4, bn = (tid & 15) << 2;

    for (int k0 = 0; k0 < DH; k0 += 16) {
#pragma unroll
        for (int h = 0; h < 2; ++h) {
            int lm = am + h * 64;
            int r = m0 + lm;
            float4 v = (r < N_EDGES)
                ? *(const float4*)(g_m1 + (size_t)r * DH + k0 + ak)
                : make_float4(0.f, 0.f, 0.f, 0.f);
            As[ak + 0][lm] = v.x; As[ak + 1][lm] = v.y;
            As[ak + 2][lm] = v.z; As[ak + 3][lm] = v.w;
        }
        {
            const float* wp = W + (size_t)(k0 + bk) * ldW + n0;
            *(float4*)&Bs[bk][bn]      = *(const float4*)(wp + bn);
            *(float4*)&Bs[bk][bn + 64] = *(const float4*)(wp + bn + 64);
        }
        __syncthreads();
        MM_BODY();
        __syncthreads();
    }

    float bset[8];
    {
        float4 b0 = *(const float4*)(bias + n0 + tn * 8);
        float4 b1 = *(const float4*)(bias + n0 + tn * 8 + 4);
        bset[0] = b0.x; bset[1] = b0.y; bset[2] = b0.z; bset[3] = b0.w;
        bset[4] = b1.x; bset[5] = b1.y; bset[6] = b1.z; bset[7] = b1.w;
    }
    const int ncol = n0 + tn * 8;
#pragma unroll
    for (int i = 0; i < 8; ++i) {
        int r = m0 + tm * 8 + i;
        if (r >= N_EDGES) continue;
        UNPACK_RELU(o, i, bset);
        if (n0 < DH) {                     // xm part 1 -> segment sum
            float* ap = g_agg + (size_t)sDst[tm * 8 + i] * DH + ncol;
#pragma unroll
            for (int j = 0; j < 8; ++j) atomicAdd(ap + j, o[j]);
        } else if (n0 < DH + DE) {         // new_e
            float* op = eout + (size_t)r * DE + (ncol - DH);
            *(float4*)op       = make_float4(o[0], o[1], o[2], o[3]);
            *(float4*)(op + 4) = make_float4(o[4], o[5], o[6], o[7]);
        } else {                           // xm part 2 -> segment sum
            float* ap = g_agg + (size_t)sDst[tm * 8 + i] * DH + (ncol - DH - DE);
#pragma unroll
            for (int j = 0; j < 8; ++j) atomicAdd(ap + j, o[j]);
        }
    }
}

// ============================================================================
// GEMM3: h = relu((agg * 1/max(cnt,1)) @ W2a + b2a)   (N x 512)@(512 x 512)
// Mean-normalization folded into the A-tile load. Grid: (4, 157).
// ============================================================================
__global__ void __launch_bounds__(256, 2) gemm3_kernel(
    const float* __restrict__ W, const float* __restrict__ bias)
{
    __shared__ float As[16][128];
    __shared__ float Bs[16][128];
    __shared__ float sInv[128];

    const int tid = threadIdx.x;
    const int n0 = blockIdx.x * 128;
    const int m0 = blockIdx.y * 128;
    const int tm = tid >> 4, tn = tid & 15;

    if (tid < 128) {
        int r = m0 + tid;
        float c = (r < N_NODES) ? g_cnt[r] : 1.f;
        sInv[tid] = 1.f / fmaxf(c, 1.f);
    }
    __syncthreads();

    ZERO_ACC();

    const int am = tid >> 2, ak = (tid & 3) << 2;
    const int bk = tid >> 4, bn = (tid & 15) << 2;

    for (int k0 = 0; k0 < DH; k0 += 16) {
#pragma unroll
        for (int h = 0; h < 2; ++h) {
            int lm = am + h * 64;
            int r = m0 + lm;
            float4 v = make_float4(0.f, 0.f, 0.f, 0.f);
            if (r < N_NODES) {
                v = *(const float4*)(g_agg + (size_t)r * DH + k0 + ak);
                float s = sInv[lm];
                v.x *= s; v.y *= s; v.z *= s; v.w *= s;
            }
            As[ak + 0][lm] = v.x; As[ak + 1][lm] = v.y;
            As[ak + 2][lm] = v.z; As[ak + 3][lm] = v.w;
        }
        {
            const float* wp = W + (size_t)(k0 + bk) * DH + n0;
            *(float4*)&Bs[bk][bn]      = *(const float4*)(wp + bn);
            *(float4*)&Bs[bk][bn + 64] = *(const float4*)(wp + bn + 64);
        }
        __syncthreads();
        MM_BODY();
        __syncthreads();
    }

    float bset[8];
    {
        float4 b0 = *(const float4*)(bias + n0 + tn * 8);
        float4 b1 = *(const float4*)(bias + n0 + tn * 8 + 4);
        bset[0] = b0.x; bset[1] = b0.y; bset[2] = b0.z; bset[3] = b0.w;
        bset[4] = b1.x; bset[5] = b1.y; bset[6] = b1.z; bset[7] = b1.w;
    }
#pragma unroll
    for (int i = 0; i < 8; ++i) {
        int r = m0 + tm * 8 + i;
        if (r >= N_NODES) continue;
        UNPACK_RELU(o, i, bset);
        float* op = g_h + (size_t)r * DH + n0 + tn * 8;
        *(float4*)op       = make_float4(o[0], o[1], o[2], o[3]);
        *(float4*)(op + 4) = make_float4(o[4], o[5], o[6], o[7]);
    }
}

// ============================================================================
// GEMM4: new_x = x + (h @ W2b + b2b)  [+ relu if not last layer]
// (N x 512)@(512 x 256). Residual folded into epilogue. Grid: (2, 157).
// ============================================================================
__global__ void __launch_bounds__(256, 2) gemm4_kernel(
    const float* __restrict__ xin,
    const float* __restrict__ W, const float* __restrict__ bias,
    float* __restrict__ xout, int do_relu)
{
    __shared__ float As[16][128];
    __shared__ float Bs[16][128];

    const int tid = threadIdx.x;
    const int n0 = blockIdx.x * 128;
    const int m0 = blockIdx.y * 128;
    const int tm = tid >> 4, tn = tid & 15;

    ZERO_ACC();

    const int am = tid >> 2, ak = (tid & 3) << 2;
    const int bk = tid >> 4, bn = (tid & 15) << 2;

    for (int k0 = 0; k0 < DH; k0 += 16) {
#pragma unroll
        for (int h = 0; h < 2; ++h) {
            int lm = am + h * 64;
            int r = m0 + lm;
            float4 v = (r < N_NODES)
                ? *(const float4*)(g_h + (size_t)r * DH + k0 + ak)
                : make_float4(0.f, 0.f, 0.f, 0.f);
            As[ak + 0][lm] = v.x; As[ak + 1][lm] = v.y;
            As[ak + 2][lm] = v.z; As[ak + 3][lm] = v.w;
        }
        {
            const float* wp = W + (size_t)(k0 + bk) * DN + n0;
            *(float4*)&Bs[bk][bn]      = *(const float4*)(wp + bn);
            *(float4*)&Bs[bk][bn + 64] = *(const float4*)(wp + bn + 64);
        }
        __syncthreads();
        MM_BODY();
        __syncthreads();
    }

    float bset[8];
    {
        float4 b0 = *(const float4*)(bias + n0 + tn * 8);
        float4 b1 = *(const float4*)(bias + n0 + tn * 8 + 4);
        bset[0] = b0.x; bset[1] = b0.y; bset[2] = b0.z; bset[3] = b0.w;
        bset[4] = b1.x; bset[5] = b1.y; bset[6] = b1.z; bset[7] = b1.w;
    }
    const int ncol = n0 + tn * 8;
#pragma unroll
    for (int i = 0; i < 8; ++i) {
        int r = m0 + tm * 8 + i;
        if (r >= N_NODES) continue;
        float4 x0 = *(const float4*)(xin + (size_t)r * DN + ncol);
        float4 x1 = *(const float4*)(xin + (size_t)r * DN + ncol + 4);
        float xv[8] = {x0.x, x0.y, x0.z, x0.w, x1.x, x1.y, x1.z, x1.w};
        float o[8];
#pragma unroll
        for (int j2 = 0; j2 < 4; ++j2) {
            float2 v = unpack2(acc[i][j2]);
            o[2 * j2]     = v.x + bset[2 * j2]     + xv[2 * j2];
            o[2 * j2 + 1] = v.y + bset[2 * j2 + 1] + xv[2 * j2 + 1];
        }
        if (do_relu) {
#pragma unroll
            for (int j = 0; j < 8; ++j) o[j] = fmaxf(o[j], 0.f);
        }
        float* op = xout + (size_t)r * DN + ncol;
        *(float4*)op       = make_float4(o[0], o[1], o[2], o[3]);
        *(float4*)(op + 4) = make_float4(o[4], o[5], o[6], o[7]);
    }
}

// ============================================================================
extern "C" void kernel_launch(void* const* d_in, const int* in_sizes, int n_in,
                              void* d_out, int out_size)
{
    (void)in_sizes; (void)n_in; (void)out_size;
    const float* node = (const float*)d_in[0];
    const float* edge = (const float*)d_in[1];
    const int*   eidx = (const int*)  d_in[2];
    const float* W1a  = (const float*)d_in[3];
    const float* b1a  = (const float*)d_in[4];
    const float* W1b  = (const float*)d_in[5];
    const float* b1b  = (const float*)d_in[6];
    const float* W2a  = (const float*)d_in[7];
    const float* b2a  = (const float*)d_in[8];
    const float* W2b  = (const float*)d_in[9];
    const float* b2b  = (const float*)d_in[10];
    float* out = (float*)d_out;

    const int* srcI = eidx;            // edges_indices[0]
    const int* dstI = eidx + N_EDGES;  // edges_indices[1]

    const int MT_E = (N_EDGES + 127) / 128;  // 782
    const int MT_N = (N_NODES + 127) / 128;  // 157

    // in-degree counts (same every layer)
    zero_cnt_kernel<<<(N_NODES + 255) / 256, 256>>>();
    count_kernel<<<(N_EDGES + 255) / 256, 256>>>(dstI);

    // device addresses of persistent buffers (taken via kernels' symbol use;
    // for host-side pointer arithmetic we only need them as launch args)
    for (int l = 0; l < NLAYERS; ++l) {
        zero_agg_kernel<<<(N_NODES * DH / 4 + 255) / 256, 256>>>();

        const float* xin = nullptr;
        const float* ein = nullptr;
        if (l == 0) { xin = node; ein = edge; }

        // For l>0 we must pass the device-global scratch addresses. Use a tiny
        // trampoline: kernels accept pointers, so fetch symbol addresses once.
        static float* p_gx = nullptr;
        static float* p_ge = nullptr;
        if (!p_gx) {
            void* tmp;
            cudaGetSymbolAddress(&tmp, g_x); p_gx = (float*)tmp;
            cudaGetSymbolAddress(&tmp, g_e); p_ge = (float*)tmp;
        }
        if (l > 0) { xin = p_gx; ein = p_ge; }

        gemm1_kernel<<<dim3(DH / 128, MT_E), 256>>>(
            xin, ein, srcI, dstI,
            W1a + (size_t)l * (2 * DN + DE) * DH, b1a + (size_t)l * DH);

        float* eout = (l == NLAYERS - 1) ? (out + (size_t)N_NODES * DN) : p_ge;
        gemm2_kernel<<<dim3((2 * DH + DE) / 128, MT_E), 256>>>(
            dstI,
            W1b + (size_t)l * DH * (2 * DH + DE), b1b + (size_t)l * (2 * DH + DE),
            eout);

        gemm3_kernel<<<dim3(DH / 128, MT_N), 256>>>(
            W2a + (size_t)l * DH * DH, b2a + (size_t)l * DH);

        float* xout = (l == NLAYERS - 1) ? out : p_gx;
        gemm4_kernel<<<dim3(DN / 128, MT_N), 256>>>(
            xin,
            W2b + (size_t)l * DH * DN, b2b + (size_t)l * DN,
            xout, (l < NLAYERS - 1) ? 1 : 0);
    }
}

// round 8
// speedup vs baseline: 1.0010x; 1.0010x over previous
#include <cuda_runtime.h>
#include <cstdint>

#define N_NODES 20000
#define N_EDGES 100000
#define DN 256
#define DE 256
#define DH 512
#define NLAYERS 2

// ---------------- scratch (device globals: allocation-free) ----------------
__device__ float g_m1 [(size_t)N_EDGES * DH];   // relu(concat @ W1a + b1a)
__device__ float g_e  [(size_t)N_EDGES * DE];   // edge features between layers
__device__ float g_x  [(size_t)N_NODES * DN];   // node features between layers
__device__ float g_agg[(size_t)N_NODES * DH];   // segment-sum accumulator
__device__ float g_h  [(size_t)N_NODES * DH];   // relu(agg_norm @ W2a + b2a)
__device__ float g_cnt[N_NODES];                // in-degree counts

typedef unsigned long long u64;

// ---------------- packed f32x2 helpers (SASS FFMA2 path) ----------------
__device__ __forceinline__ u64 pack2(float lo, float hi) {
    u64 r;
    asm("mov.b64 %0, {%1, %2};" : "=l"(r) : "f"(lo), "f"(hi));
    return r;
}
__device__ __forceinline__ float2 unpack2(u64 v) {
    float2 r;
    asm("mov.b64 {%0, %1}, %2;" : "=f"(r.x), "=f"(r.y) : "l"(v));
    return r;
}
__device__ __forceinline__ void ffma2(u64& d, u64 a, u64 b) {
    asm("fma.rn.f32x2 %0, %1, %2, %0;" : "+l"(d) : "l"(a), "l"(b));
}

// Inner product body over one BK=16 shared tile.
// acc[i][j2] packs output cols (2*j2, 2*j2+1); B pairs come free from LDS.128.
#define MM_BODY()                                                          \
    _Pragma("unroll")                                                      \
    for (int kk = 0; kk < 16; ++kk) {                                      \
        float4 a0 = *(const float4*)&As[kk][tm * 8];                       \
        float4 a1 = *(const float4*)&As[kk][tm * 8 + 4];                   \
        ulonglong2 b01 = *(const ulonglong2*)&Bs[kk][tn * 8];              \
        ulonglong2 b23 = *(const ulonglong2*)&Bs[kk][tn * 8 + 4];          \
        u64 bb0 = b01.x, bb1 = b01.y, bb2 = b23.x, bb3 = b23.y;            \
        float av[8] = {a0.x, a0.y, a0.z, a0.w, a1.x, a1.y, a1.z, a1.w};    \
        _Pragma("unroll")                                                  \
        for (int i = 0; i < 8; ++i) {                                      \
            u64 ar = pack2(av[i], av[i]);                                  \
            ffma2(acc[i][0], ar, bb0);                                     \
            ffma2(acc[i][1], ar, bb1);                                     \
            ffma2(acc[i][2], ar, bb2);                                     \
            ffma2(acc[i][3], ar, bb3);                                     \
        }                                                                  \
    }

#define ZERO_ACC()                                                         \
    u64 acc[8][4];                                                         \
    _Pragma("unroll")                                                      \
    for (int i = 0; i < 8; ++i)                                            \
        _Pragma("unroll")                                                  \
        for (int j = 0; j < 4; ++j) acc[i][j] = 0ull;

#define UNPACK_RELU(o, i, bset)                                            \
    float o[8];                                                            \
    _Pragma("unroll")                                                      \
    for (int j2 = 0; j2 < 4; ++j2) {                                       \
        float2 v = unpack2(acc[i][j2]);                                    \
        o[2 * j2]     = fmaxf(v.x + bset[2 * j2], 0.f);                    \
        o[2 * j2 + 1] = fmaxf(v.y + bset[2 * j2 + 1], 0.f);                \
    }

// ---------------- small utility kernels ----------------
__global__ void zero_cnt_kernel() {
    int i = blockIdx.x * blockDim.x + threadIdx.x;
    if (i < N_NODES) g_cnt[i] = 0.f;
}
__global__ void zero_agg_kernel() {
    int i = blockIdx.x * blockDim.x + threadIdx.x;
    if (i < N_NODES * DH / 4)
        ((float4*)g_agg)[i] = make_float4(0.f, 0.f, 0.f, 0.f);
}
__global__ void count_kernel(const int* __restrict__ dstI) {
    int e = blockIdx.x * blockDim.x + threadIdx.x;
    if (e < N_EDGES) atomicAdd(&g_cnt[dstI[e]], 1.f);
}

// ============================================================================
// GEMM1: m1 = relu([x[dst] | e | x[src]] @ W1a + b1a)   (E x 768)@(768 x 512)
// A rows are gathered on the fly. Grid: (4 N-tiles, 782 M-tiles).
// ============================================================================
__global__ void __launch_bounds__(256, 2) gemm1_kernel(
    const float* __restrict__ xin, const float* __restrict__ ein,
    const int* __restrict__ srcI, const int* __restrict__ dstI,
    const float* __restrict__ W, const float* __restrict__ bias)
{
    __shared__ float As[16][128];
    __shared__ float Bs[16][128];
    __shared__ int sDst[128], sSrc[128];

    const int tid = threadIdx.x;
    const int n0 = blockIdx.x * 128;
    const int m0 = blockIdx.y * 128;
    const int tm = tid >> 4, tn = tid & 15;

    if (tid < 128) {
        int r = m0 + tid;
        sDst[tid] = (r < N_EDGES) ? dstI[r] : 0;
        sSrc[tid] = (r < N_EDGES) ? srcI[r] : 0;
    }
    __syncthreads();

    ZERO_ACC();

    const int am = tid >> 2, ak = (tid & 3) << 2;
    const int bk = tid >> 4, bn = (tid & 15) << 2;

    for (int k0 = 0; k0 < 2 * DN + DE; k0 += 16) {
#pragma unroll
        for (int h = 0; h < 2; ++h) {
            int lm = am + h * 64;
            int r = m0 + lm;
            float4 v = make_float4(0.f, 0.f, 0.f, 0.f);
            if (r < N_EDGES) {
                int kg = k0 + ak;
                const float* p;
                if (kg < DN)            p = xin + (size_t)sDst[lm] * DN + kg;
                else if (kg < DN + DE)  p = ein + (size_t)r * DE + (kg - DN);
                else                    p = xin + (size_t)sSrc[lm] * DN + (kg - DN - DE);
                v = *(const float4*)p;
            }
            As[ak + 0][lm] = v.x; As[ak + 1][lm] = v.y;
            As[ak + 2][lm] = v.z; As[ak + 3][lm] = v.w;
        }
        {
            const float* wp = W + (size_t)(k0 + bk) * DH + n0;
            *(float4*)&Bs[bk][bn]      = *(const float4*)(wp + bn);
            *(float4*)&Bs[bk][bn + 64] = *(const float4*)(wp + bn + 64);
        }
        __syncthreads();
        MM_BODY();
        __syncthreads();
    }

    float bset[8];
    {
        float4 b0 = *(const float4*)(bias + n0 + tn * 8);
        float4 b1 = *(const float4*)(bias + n0 + tn * 8 + 4);
        bset[0] = b0.x; bset[1] = b0.y; bset[2] = b0.z; bset[3] = b0.w;
        bset[4] = b1.x; bset[5] = b1.y; bset[6] = b1.z; bset[7] = b1.w;
    }
#pragma unroll
    for (int i = 0; i < 8; ++i) {
        int r = m0 + tm * 8 + i;
        if (r >= N_EDGES) continue;
        UNPACK_RELU(o, i, bset);
        float* op = g_m1 + (size_t)r * DH + n0 + tn * 8;
        *(float4*)op       = make_float4(o[0], o[1], o[2], o[3]);
        *(float4*)(op + 4) = make_float4(o[4], o[5], o[6], o[7]);
    }
}

// ============================================================================
// GEMM2: m2 = relu(m1 @ W1b + b1b)   (E x 512)@(512 x 1280)
// Epilogue by column region: [0,512)+[768,1280) -> atomicAdd into g_agg[dst]
// (sum of the two relu branches == xm, order-free); [512,768) -> new_e.
// Grid: (10 N-tiles, 782 M-tiles).
// ============================================================================
__global__ void __launch_bounds__(256, 2) gemm2_kernel(
    const int* __restrict__ dstI,
    const float* __restrict__ W, const float* __restrict__ bias,
    float* __restrict__ eout)
{
    __shared__ float As[16][128];
    __shared__ float Bs[16][128];
    __shared__ int sDst[128];

    const int tid = threadIdx.x;
    const int n0 = blockIdx.x * 128;
    const int m0 = blockIdx.y * 128;
    const int tm = tid >> 4, tn = tid & 15;
    const int ldW = 2 * DH + DE;  // 1280

    if (tid < 128) {
        int r = m0 + tid;
        sDst[tid] = (r < N_EDGES) ? dstI[r] : 0;
    }
    __syncthreads();

    ZERO_ACC();

    const int am = tid >> 2, ak = (tid & 3) << 2;
    const int bk = tid >> 4, bn = (tid & 15) << 2;

    for (int k0 = 0; k0 < DH; k0 += 16) {
#pragma unroll
        for (int h = 0; h < 2; ++h) {
            int lm = am + h * 64;
            int r = m0 + lm;
            float4 v = (r < N_EDGES)
                ? *(const float4*)(g_m1 + (size_t)r * DH + k0 + ak)
                : make_float4(0.f, 0.f, 0.f, 0.f);
            As[ak + 0][lm] = v.x; As[ak + 1][lm] = v.y;
            As[ak + 2][lm] = v.z; As[ak + 3][lm] = v.w;
        }
        {
            const float* wp = W + (size_t)(k0 + bk) * ldW + n0;
            *(float4*)&Bs[bk][bn]      = *(const float4*)(wp + bn);
            *(float4*)&Bs[bk][bn + 64] = *(const float4*)(wp + bn + 64);
        }
        __syncthreads();
        MM_BODY();
        __syncthreads();
    }

    float bset[8];
    {
        float4 b0 = *(const float4*)(bias + n0 + tn * 8);
        float4 b1 = *(const float4*)(bias + n0 + tn * 8 + 4);
        bset[0] = b0.x; bset[1] = b0.y; bset[2] = b0.z; bset[3] = b0.w;
        bset[4] = b1.x; bset[5] = b1.y; bset[6] = b1.z; bset[7] = b1.w;
    }
    const int ncol = n0 + tn * 8;
#pragma unroll
    for (int i = 0; i < 8; ++i) {
        int r = m0 + tm * 8 + i;
        if (r >= N_EDGES) continue;
        UNPACK_RELU(o, i, bset);
        if (n0 < DH) {                     // xm part 1 -> segment sum
            float* ap = g_agg + (size_t)sDst[tm * 8 + i] * DH + ncol;
#pragma unroll
            for (int j = 0; j < 8; ++j) atomicAdd(ap + j, o[j]);
        } else if (n0 < DH + DE) {         // new_e
            float* op = eout + (size_t)r * DE + (ncol - DH);
            *(float4*)op       = make_float4(o[0], o[1], o[2], o[3]);
            *(float4*)(op + 4) = make_float4(o[4], o[5], o[6], o[7]);
        } else {                           // xm part 2 -> segment sum
            float* ap = g_agg + (size_t)sDst[tm * 8 + i] * DH + (ncol - DH - DE);
#pragma unroll
            for (int j = 0; j < 8; ++j) atomicAdd(ap + j, o[j]);
        }
    }
}

// ============================================================================
// GEMM3: h = relu((agg * 1/max(cnt,1)) @ W2a + b2a)   (N x 512)@(512 x 512)
// Mean-normalization folded into the A-tile load. Grid: (4, 157).
// ============================================================================
__global__ void __launch_bounds__(256, 2) gemm3_kernel(
    const float* __restrict__ W, const float* __restrict__ bias)
{
    __shared__ float As[16][128];
    __shared__ float Bs[16][128];
    __shared__ float sInv[128];

    const int tid = threadIdx.x;
    const int n0 = blockIdx.x * 128;
    const int m0 = blockIdx.y * 128;
    const int tm = tid >> 4, tn = tid & 15;

    if (tid < 128) {
        int r = m0 + tid;
        float c = (r < N_NODES) ? g_cnt[r] : 1.f;
        sInv[tid] = 1.f / fmaxf(c, 1.f);
    }
    __syncthreads();

    ZERO_ACC();

    const int am = tid >> 2, ak = (tid & 3) << 2;
    const int bk = tid >> 4, bn = (tid & 15) << 2;

    for (int k0 = 0; k0 < DH; k0 += 16) {
#pragma unroll
        for (int h = 0; h < 2; ++h) {
            int lm = am + h * 64;
            int r = m0 + lm;
            float4 v = make_float4(0.f, 0.f, 0.f, 0.f);
            if (r < N_NODES) {
                v = *(const float4*)(g_agg + (size_t)r * DH + k0 + ak);
                float s = sInv[lm];
                v.x *= s; v.y *= s; v.z *= s; v.w *= s;
            }
            As[ak + 0][lm] = v.x; As[ak + 1][lm] = v.y;
            As[ak + 2][lm] = v.z; As[ak + 3][lm] = v.w;
        }
        {
            const float* wp = W + (size_t)(k0 + bk) * DH + n0;
            *(float4*)&Bs[bk][bn]      = *(const float4*)(wp + bn);
            *(float4*)&Bs[bk][bn + 64] = *(const float4*)(wp + bn + 64);
        }
        __syncthreads();
        MM_BODY();
        __syncthreads();
    }

    float bset[8];
    {
        float4 b0 = *(const float4*)(bias + n0 + tn * 8);
        float4 b1 = *(const float4*)(bias + n0 + tn * 8 + 4);
        bset[0] = b0.x; bset[1] = b0.y; bset[2] = b0.z; bset[3] = b0.w;
        bset[4] = b1.x; bset[5] = b1.y; bset[6] = b1.z; bset[7] = b1.w;
    }
#pragma unroll
    for (int i = 0; i < 8; ++i) {
        int r = m0 + tm * 8 + i;
        if (r >= N_NODES) continue;
        UNPACK_RELU(o, i, bset);
        float* op = g_h + (size_t)r * DH + n0 + tn * 8;
        *(float4*)op       = make_float4(o[0], o[1], o[2], o[3]);
        *(float4*)(op + 4) = make_float4(o[4], o[5], o[6], o[7]);
    }
}

// ============================================================================
// GEMM4: new_x = x + (h @ W2b + b2b)  [+ relu if not last layer]
// (N x 512)@(512 x 256). Residual folded into epilogue. Grid: (2, 157).
// ============================================================================
__global__ void __launch_bounds__(256, 2) gemm4_kernel(
    const float* __restrict__ xin,
    const float* __restrict__ W, const float* __restrict__ bias,
    float* __restrict__ xout, int do_relu)
{
    __shared__ float As[16][128];
    __shared__ float Bs[16][128];

    const int tid = threadIdx.x;
    const int n0 = blockIdx.x * 128;
    const int m0 = blockIdx.y * 128;
    const int tm = tid >> 4, tn = tid & 15;

    ZERO_ACC();

    const int am = tid >> 2, ak = (tid & 3) << 2;
    const int bk = tid >> 4, bn = (tid & 15) << 2;

    for (int k0 = 0; k0 < DH; k0 += 16) {
#pragma unroll
        for (int h = 0; h < 2; ++h) {
            int lm = am + h * 64;
            int r = m0 + lm;
            float4 v = (r < N_NODES)
                ? *(const float4*)(g_h + (size_t)r * DH + k0 + ak)
                : make_float4(0.f, 0.f, 0.f, 0.f);
            As[ak + 0][lm] = v.x; As[ak + 1][lm] = v.y;
            As[ak + 2][lm] = v.z; As[ak + 3][lm] = v.w;
        }
        {
            const float* wp = W + (size_t)(k0 + bk) * DN + n0;
            *(float4*)&Bs[bk][bn]      = *(const float4*)(wp + bn);
            *(float4*)&Bs[bk][bn + 64] = *(const float4*)(wp + bn + 64);
        }
        __syncthreads();
        MM_BODY();
        __syncthreads();
    }

    float bset[8];
    {
        float4 b0 = *(const float4*)(bias + n0 + tn * 8);
        float4 b1 = *(const float4*)(bias + n0 + tn * 8 + 4);
        bset[0] = b0.x; bset[1] = b0.y; bset[2] = b0.z; bset[3] = b0.w;
        bset[4] = b1.x; bset[5] = b1.y; bset[6] = b1.z; bset[7] = b1.w;
    }
    const int ncol = n0 + tn * 8;
#pragma unroll
    for (int i = 0; i < 8; ++i) {
        int r = m0 + tm * 8 + i;
        if (r >= N_NODES) continue;
        float4 x0 = *(const float4*)(xin + (size_t)r * DN + ncol);
        float4 x1 = *(const float4*)(xin + (size_t)r * DN + ncol + 4);
        float xv[8] = {x0.x, x0.y, x0.z, x0.w, x1.x, x1.y, x1.z, x1.w};
        float o[8];
#pragma unroll
        for (int j2 = 0; j2 < 4; ++j2) {
            float2 v = unpack2(acc[i][j2]);
            o[2 * j2]     = v.x + bset[2 * j2]     + xv[2 * j2];
            o[2 * j2 + 1] = v.y + bset[2 * j2 + 1] + xv[2 * j2 + 1];
        }
        if (do_relu) {
#pragma unroll
            for (int j = 0; j < 8; ++j) o[j] = fmaxf(o[j], 0.f);
        }
        float* op = xout + (size_t)r * DN + ncol;
        *(float4*)op       = make_float4(o[0], o[1], o[2], o[3]);
        *(float4*)(op + 4) = make_float4(o[4], o[5], o[6], o[7]);
    }
}

// ============================================================================
extern "C" void kernel_launch(void* const* d_in, const int* in_sizes, int n_in,
                              void* d_out, int out_size)
{
    (void)in_sizes; (void)n_in; (void)out_size;
    const float* node = (const float*)d_in[0];
    const float* edge = (const float*)d_in[1];
    const int*   eidx = (const int*)  d_in[2];
    const float* W1a  = (const float*)d_in[3];
    const float* b1a  = (const float*)d_in[4];
    const float* W1b  = (const float*)d_in[5];
    const float* b1b  = (const float*)d_in[6];
    const float* W2a  = (const float*)d_in[7];
    const float* b2a  = (const float*)d_in[8];
    const float* W2b  = (const float*)d_in[9];
    const float* b2b  = (const float*)d_in[10];
    float* out = (float*)d_out;

    const int* srcI = eidx;            // edges_indices[0]
    const int* dstI = eidx + N_EDGES;  // edges_indices[1]

    const int MT_E = (N_EDGES + 127) / 128;  // 782
    const int MT_N = (N_NODES + 127) / 128;  // 157

    // in-degree counts (same every layer)
    zero_cnt_kernel<<<(N_NODES + 255) / 256, 256>>>();
    count_kernel<<<(N_EDGES + 255) / 256, 256>>>(dstI);

    // device addresses of persistent buffers (taken via kernels' symbol use;
    // for host-side pointer arithmetic we only need them as launch args)
    for (int l = 0; l < NLAYERS; ++l) {
        zero_agg_kernel<<<(N_NODES * DH / 4 + 255) / 256, 256>>>();

        const float* xin = nullptr;
        const float* ein = nullptr;
        if (l == 0) { xin = node; ein = edge; }

        // For l>0 we must pass the device-global scratch addresses. Use a tiny
        // trampoline: kernels accept pointers, so fetch symbol addresses once.
        static float* p_gx = nullptr;
        static float* p_ge = nullptr;
        if (!p_gx) {
            void* tmp;
            cudaGetSymbolAddress(&tmp, g_x); p_gx = (float*)tmp;
            cudaGetSymbolAddress(&tmp, g_e); p_ge = (float*)tmp;
        }
        if (l > 0) { xin = p_gx; ein = p_ge; }

        gemm1_kernel<<<dim3(DH / 128, MT_E), 256>>>(
            xin, ein, srcI, dstI,
            W1a + (size_t)l * (2 * DN + DE) * DH, b1a + (size_t)l * DH);

        float* eout = (l == NLAYERS - 1) ? (out + (size_t)N_NODES * DN) : p_ge;
        gemm2_kernel<<<dim3((2 * DH + DE) / 128, MT_E), 256>>>(
            dstI,
            W1b + (size_t)l * DH * (2 * DH + DE), b1b + (size_t)l * (2 * DH + DE),
            eout);

        gemm3_kernel<<<dim3(DH / 128, MT_N), 256>>>(
            W2a + (size_t)l * DH * DH, b2a + (size_t)l * DH);

        float* xout = (l == NLAYERS - 1) ? out : p_gx;
        gemm4_kernel<<<dim3(DN / 128, MT_N), 256>>>(
            xin,
            W2b + (size_t)l * DH * DN, b2b + (size_t)l * DN,
            xout, (l < NLAYERS - 1) ? 1 : 0);
    }
}

// round 11
// speedup vs baseline: 2.0686x; 2.0665x over previous
#include <cuda_runtime.h>
#include <cuda_bf16.h>
#include <cstdint>

#define N_NODES 20000
#define N_EDGES 100000
#define DN 256
#define DE 256
#define DH 512
#define NLAYERS 2

// ---------------- scratch (device globals: allocation-free) ----------------
__device__ float g_m1 [(size_t)N_EDGES * DH];
__device__ float g_e  [(size_t)N_EDGES * DE];
__device__ float g_x  [(size_t)N_NODES * DN];
__device__ float g_agg[(size_t)N_NODES * DH];
__device__ float g_h  [(size_t)N_NODES * DH];
__device__ float g_cnt[N_NODES];

// transposed + bf16-split weights [N][K] K-major, per layer
#define OFF_W1A 0
#define OFF_W1B (DH * (2 * DN + DE))
#define OFF_W2A (OFF_W1B + (2 * DH + DE) * DH)
#define OFF_W2B (OFF_W2A + DH * DH)
#define WT_LAYER (OFF_W2B + DH * DN)               // 1441792
__device__ __align__(16) uint16_t g_Wh[(size_t)NLAYERS * WT_LAYER];
__device__ __align__(16) uint16_t g_Wl[(size_t)NLAYERS * WT_LAYER];

// ---------------- helpers ----------------
__device__ __forceinline__ uint32_t smem_to_u32(const void* p) {
    uint32_t a;
    asm("{ .reg .u64 t; cvta.to.shared.u64 t, %1; cvt.u32.u64 %0, t; }"
        : "=r"(a) : "l"(p));
    return a;
}

// pack (lo, hi) floats -> bf16x2 (lo in low half)
__device__ __forceinline__ uint32_t cvt_bf16x2(float lo, float hi) {
    uint32_t r;
    asm("cvt.rn.bf16x2.f32 %0, %1, %2;" : "=r"(r) : "f"(hi), "f"(lo));
    return r;
}

// split float4 into bf16 hi/lo pairs, store 8B each
__device__ __forceinline__ void split_store(float4 v, char* hiP, char* loP) {
    uint32_t h0 = cvt_bf16x2(v.x, v.y);
    uint32_t h1 = cvt_bf16x2(v.z, v.w);
    float r0 = v.x - __uint_as_float(h0 << 16);
    float r1 = v.y - __uint_as_float(h0 & 0xFFFF0000u);
    float r2 = v.z - __uint_as_float(h1 << 16);
    float r3 = v.w - __uint_as_float(h1 & 0xFFFF0000u);
    uint32_t l0 = cvt_bf16x2(r0, r1);
    uint32_t l1 = cvt_bf16x2(r2, r3);
    *(uint2*)hiP = make_uint2(h0, h1);
    *(uint2*)loP = make_uint2(l0, l1);
}

__device__ __forceinline__ void ldsm4(uint32_t addr, uint32_t* r) {
    asm volatile("ldmatrix.sync.aligned.m8n8.x4.shared.b16 {%0,%1,%2,%3}, [%4];"
                 : "=r"(r[0]), "=r"(r[1]), "=r"(r[2]), "=r"(r[3]) : "r"(addr));
}

__device__ __forceinline__ void mma_bf16(float* c, const uint32_t* a,
                                         uint32_t b0, uint32_t b1) {
    asm volatile("mma.sync.aligned.m16n8k16.row.col.f32.bf16.bf16.f32 "
                 "{%0,%1,%2,%3}, {%4,%5,%6,%7}, {%8,%9}, {%0,%1,%2,%3};"
                 : "+f"(c[0]), "+f"(c[1]), "+f"(c[2]), "+f"(c[3])
                 : "r"(a[0]), "r"(a[1]), "r"(a[2]), "r"(a[3]), "r"(b0), "r"(b1));
}

__device__ __forceinline__ void red_add_v2(float* p, float x, float y) {
    asm volatile("red.global.add.v2.f32 [%0], {%1, %2};"
                 :: "l"(p), "f"(x), "f"(y) : "memory");
}

// ---------------- dynamic smem layout ----------------
#define SM_BIAS   0       // 128 floats
#define SM_DST    512     // 128 ints
#define SM_SRC    1024
#define SM_INV    1536
#define SM_TILES  2048
#define PITCH     80                    // bytes per 32-halves row (+pad)
#define TILE_B    (128 * PITCH)         // 10240
#define STAGE_B   (4 * TILE_B)          // Ah Al Bh Bl
#define SMEM_TOTAL (SM_TILES + 2 * STAGE_B)  // 83968

// ---------------- utility kernels ----------------
__global__ void zero_cnt_kernel() {
    int i = blockIdx.x * blockDim.x + threadIdx.x;
    if (i < N_NODES) g_cnt[i] = 0.f;
}
__global__ void zero_agg_kernel() {
    int i = blockIdx.x * blockDim.x + threadIdx.x;
    if (i < N_NODES * DH / 4)
        ((float4*)g_agg)[i] = make_float4(0.f, 0.f, 0.f, 0.f);
}
__global__ void count_kernel(const int* __restrict__ dstI) {
    int e = blockIdx.x * blockDim.x + threadIdx.x;
    if (e < N_EDGES) atomicAdd(&g_cnt[dstI[e]], 1.f);
}

// W [K][N] row-major -> Wh/Wl [N][K] bf16 hi/lo split
__global__ void transpose_split_kernel(const float* __restrict__ src,
                                       uint16_t* __restrict__ dh,
                                       uint16_t* __restrict__ dl,
                                       int K, int N) {
    __shared__ float t[32][33];
    int bx = blockIdx.x * 32, by = blockIdx.y * 32;
    int tx = threadIdx.x, ty = threadIdx.y;
#pragma unroll
    for (int j = 0; j < 32; j += 8) {
        int k = by + ty + j, n = bx + tx;
        t[ty + j][tx] = (k < K && n < N) ? src[(size_t)k * N + n] : 0.f;
    }
    __syncthreads();
#pragma unroll
    for (int j = 0; j < 32; j += 8) {
        int n = bx + ty + j, k = by + tx;
        if (n < N && k < K) {
            float f = t[tx][ty + j];
            __nv_bfloat16 h = __float2bfloat16(f);
            float fh = __bfloat162float(h);
            __nv_bfloat16 lo = __float2bfloat16(f - fh);
            dh[(size_t)n * K + k] = __bfloat16_as_ushort(h);
            dl[(size_t)n * K + k] = __bfloat16_as_ushort(lo);
        }
    }
}

// ---------------- shared 3x-bf16 mma.sync mainloop ----------------
// 128x128 CTA tile, BK=32 chunks, 8 warps (4 M x 2 N), warp tile 32x64.
// C[i][j][4]: i = m16 tile (2), j = n8 tile (8).
template <int KDIM, class AL>
__device__ __forceinline__ void mainloop_mma(
    char* smem, const uint16_t* __restrict__ Wh, const uint16_t* __restrict__ Wl,
    int n0, AL aload, float C[2][8][4])
{
    const int tid = threadIdx.x;
    const int lane = tid & 31, warp = tid >> 5;
    const int wm = warp & 3, wn = warp >> 2;
    const int frow = tid >> 3, fcc = tid & 7;
    const uint32_t sb = smem_to_u32(smem);

    float4 pa[4];
    uint2 pbh[4], pbl[4];
    auto loadg = [&](int c) {
        const int k0 = c * 32;
#pragma unroll
        for (int i = 0; i < 4; ++i) {
            int row = frow + 32 * i;
            pa[i] = aload(row, k0 + fcc * 4);
            size_t bo = (size_t)(n0 + row) * KDIM + k0 + fcc * 4;
            pbh[i] = *(const uint2*)(Wh + bo);
            pbl[i] = *(const uint2*)(Wl + bo);
        }
    };
    loadg(0);

    constexpr int NC = KDIM / 32;
    for (int c = 0; c < NC; ++c) {
        const int st = c & 1;
        char* Ah = smem + SM_TILES + st * STAGE_B;
        char* Al = Ah + TILE_B;
        char* Bh = Al + TILE_B;
        char* Bl = Bh + TILE_B;
        __syncthreads();
#pragma unroll
        for (int i = 0; i < 4; ++i) {
            int row = frow + 32 * i;
            int off = row * PITCH + fcc * 8;
            split_store(pa[i], Ah + off, Al + off);
            *(uint2*)(Bh + off) = pbh[i];
            *(uint2*)(Bl + off) = pbl[i];
        }
        __syncthreads();
        if (c + 1 < NC) loadg(c + 1);

        const uint32_t sAh = sb + SM_TILES + st * STAGE_B;
        const uint32_t sAl = sAh + TILE_B;
        const uint32_t sBh = sAl + TILE_B;
        const uint32_t sBl = sBh + TILE_B;
        const int lrow = lane & 15;
        const int lk = (lane >> 4) * 16;
#pragma unroll
        for (int ks = 0; ks < 2; ++ks) {
            uint32_t ah[2][4], al[2][4];
#pragma unroll
            for (int i = 0; i < 2; ++i) {
                uint32_t ao = (uint32_t)(32 * wm + 16 * i + lrow) * PITCH + ks * 32 + lk;
                ldsm4(sAh + ao, ah[i]);
                ldsm4(sAl + ao, al[i]);
            }
#pragma unroll
            for (int g = 0; g < 4; ++g) {
                uint32_t bo = (uint32_t)(64 * wn + 16 * g + lrow) * PITCH + ks * 32 + lk;
                uint32_t bh[4], bl[4];
                ldsm4(sBh + bo, bh);
                ldsm4(sBl + bo, bl);
#pragma unroll
                for (int i = 0; i < 2; ++i) {
                    mma_bf16(C[i][2 * g],     ah[i], bh[0], bh[2]);
                    mma_bf16(C[i][2 * g + 1], ah[i], bh[1], bh[3]);
                    mma_bf16(C[i][2 * g],     al[i], bh[0], bh[2]);
                    mma_bf16(C[i][2 * g + 1], al[i], bh[1], bh[3]);
                    mma_bf16(C[i][2 * g],     ah[i], bl[0], bl[2]);
                    mma_bf16(C[i][2 * g + 1], ah[i], bl[1], bl[3]);
                }
            }
        }
    }
    __syncthreads();
}

#define ZERO_C() \
    float C[2][8][4]; \
    _Pragma("unroll") for (int i = 0; i < 2; ++i) \
    _Pragma("unroll") for (int j = 0; j < 8; ++j) \
    _Pragma("unroll") for (int q = 0; q < 4; ++q) C[i][j][q] = 0.f;

// epilogue index helpers: per (i, h, j) element pair
// row_local = 32*wm + 16*i + 8*h + lane/4 ; col_local = 64*wn + 8*j + 2*(lane&3)

// ============================================================================
// GEMM1: m1 = relu([x[dst]|e|x[src]] @ W1a + b1a)   (E x 768)@(768 x 512)
// ============================================================================
__global__ void __launch_bounds__(256, 1) g1_kernel(
    const float* __restrict__ xin, const float* __restrict__ ein,
    const int* __restrict__ srcI, const int* __restrict__ dstI,
    const uint16_t* __restrict__ Wh, const uint16_t* __restrict__ Wl,
    const float* __restrict__ bias)
{
    extern __shared__ char smem[];
    const int tid = threadIdx.x;
    const int n0 = blockIdx.x * 128, m0 = blockIdx.y * 128;
    float* biasS = (float*)(smem + SM_BIAS);
    int* sDst = (int*)(smem + SM_DST);
    int* sSrc = (int*)(smem + SM_SRC);
    if (tid < 128) {
        biasS[tid] = bias[n0 + tid];
        int r = m0 + tid;
        sDst[tid] = (r < N_EDGES) ? dstI[r] : 0;
        sSrc[tid] = (r < N_EDGES) ? srcI[r] : 0;
    }
    __syncthreads();

    ZERO_C();
    auto aload = [&](int row, int kg) -> float4 {
        int r = m0 + row;
        if (r >= N_EDGES) return make_float4(0.f, 0.f, 0.f, 0.f);
        const float* p;
        if (kg < DN)           p = xin + (size_t)sDst[row] * DN + kg;
        else if (kg < DN + DE) p = ein + (size_t)r * DE + (kg - DN);
        else                   p = xin + (size_t)sSrc[row] * DN + (kg - DN - DE);
        return *(const float4*)p;
    };
    mainloop_mma<2 * DN + DE>(smem, Wh, Wl, n0, aload, C);

    const int lane = tid & 31, warp = tid >> 5;
    const int wm = warp & 3, wn = warp >> 2;
#pragma unroll
    for (int i = 0; i < 2; ++i)
#pragma unroll
    for (int h = 0; h < 2; ++h) {
        int rl = 32 * wm + 16 * i + 8 * h + (lane >> 2);
        int r = m0 + rl;
        if (r >= N_EDGES) continue;
        float* orow = g_m1 + (size_t)r * DH + n0;
#pragma unroll
        for (int j = 0; j < 8; ++j) {
            int cl = 64 * wn + 8 * j + 2 * (lane & 3);
            float2 o;
            o.x = fmaxf(C[i][j][2 * h + 0] + biasS[cl + 0], 0.f);
            o.y = fmaxf(C[i][j][2 * h + 1] + biasS[cl + 1], 0.f);
            *(float2*)(orow + cl) = o;
        }
    }
}

// ============================================================================
// GEMM2: relu(m1 @ W1b + b1b)   (E x 512)@(512 x 1280)
// cols [0,512)+[768,1280) -> red.v2 into g_agg[dst]; [512,768) -> new_e
// ============================================================================
__global__ void __launch_bounds__(256, 1) g2_kernel(
    const int* __restrict__ dstI,
    const uint16_t* __restrict__ Wh, const uint16_t* __restrict__ Wl,
    const float* __restrict__ bias, float* __restrict__ eout)
{
    extern __shared__ char smem[];
    const int tid = threadIdx.x;
    const int n0 = blockIdx.x * 128, m0 = blockIdx.y * 128;
    float* biasS = (float*)(smem + SM_BIAS);
    int* sDst = (int*)(smem + SM_DST);
    if (tid < 128) {
        biasS[tid] = bias[n0 + tid];
        int r = m0 + tid;
        sDst[tid] = (r < N_EDGES) ? dstI[r] : 0;
    }
    __syncthreads();

    ZERO_C();
    auto aload = [&](int row, int kg) -> float4 {
        int r = m0 + row;
        if (r >= N_EDGES) return make_float4(0.f, 0.f, 0.f, 0.f);
        return *(const float4*)(g_m1 + (size_t)r * DH + kg);
    };
    mainloop_mma<DH>(smem, Wh, Wl, n0, aload, C);

    const int lane = tid & 31, warp = tid >> 5;
    const int wm = warp & 3, wn = warp >> 2;
    const int mode = (n0 < DH) ? 0 : ((n0 < DH + DE) ? 1 : 2);
    const int aggc0 = (mode == 2) ? (n0 - DH - DE) : n0;
#pragma unroll
    for (int i = 0; i < 2; ++i)
#pragma unroll
    for (int h = 0; h < 2; ++h) {
        int rl = 32 * wm + 16 * i + 8 * h + (lane >> 2);
        int r = m0 + rl;
        if (r >= N_EDGES) continue;
        int dn = sDst[rl];
#pragma unroll
        for (int j = 0; j < 8; ++j) {
            int cl = 64 * wn + 8 * j + 2 * (lane & 3);
            float ox = fmaxf(C[i][j][2 * h + 0] + biasS[cl + 0], 0.f);
            float oy = fmaxf(C[i][j][2 * h + 1] + biasS[cl + 1], 0.f);
            if (mode == 1) {
                *(float2*)(eout + (size_t)r * DE + (n0 - DH) + cl) = make_float2(ox, oy);
            } else {
                red_add_v2(g_agg + (size_t)dn * DH + aggc0 + cl, ox, oy);
            }
        }
    }
}

// ============================================================================
// GEMM3: h = relu((agg/max(cnt,1)) @ W2a + b2a)   (N x 512)@(512 x 512)
// ============================================================================
__global__ void __launch_bounds__(256, 1) g3_kernel(
    const uint16_t* __restrict__ Wh, const uint16_t* __restrict__ Wl,
    const float* __restrict__ bias)
{
    extern __shared__ char smem[];
    const int tid = threadIdx.x;
    const int n0 = blockIdx.x * 128, m0 = blockIdx.y * 128;
    float* biasS = (float*)(smem + SM_BIAS);
    float* sInv = (float*)(smem + SM_INV);
    if (tid < 128) {
        biasS[tid] = bias[n0 + tid];
        int r = m0 + tid;
        float c = (r < N_NODES) ? g_cnt[r] : 1.f;
        sInv[tid] = 1.f / fmaxf(c, 1.f);
    }
    __syncthreads();

    ZERO_C();
    auto aload = [&](int row, int kg) -> float4 {
        int r = m0 + row;
        if (r >= N_NODES) return make_float4(0.f, 0.f, 0.f, 0.f);
        float4 v = *(const float4*)(g_agg + (size_t)r * DH + kg);
        float s = sInv[row];
        v.x *= s; v.y *= s; v.z *= s; v.w *= s;
        return v;
    };
    mainloop_mma<DH>(smem, Wh, Wl, n0, aload, C);

    const int lane = tid & 31, warp = tid >> 5;
    const int wm = warp & 3, wn = warp >> 2;
#pragma unroll
    for (int i = 0; i < 2; ++i)
#pragma unroll
    for (int h = 0; h < 2; ++h) {
        int rl = 32 * wm + 16 * i + 8 * h + (lane >> 2);
        int r = m0 + rl;
        if (r >= N_NODES) continue;
        float* orow = g_h + (size_t)r * DH + n0;
#pragma unroll
        for (int j = 0; j < 8; ++j) {
            int cl = 64 * wn + 8 * j + 2 * (lane & 3);
            float2 o;
            o.x = fmaxf(C[i][j][2 * h + 0] + biasS[cl + 0], 0.f);
            o.y = fmaxf(C[i][j][2 * h + 1] + biasS[cl + 1], 0.f);
            *(float2*)(orow + cl) = o;
        }
    }
}

// ============================================================================
// GEMM4: new_x = x + (h @ W2b + b2b)  [+relu]   (N x 512)@(512 x 256)
// ============================================================================
__global__ void __launch_bounds__(256, 1) g4_kernel(
    const float* __restrict__ xin,
    const uint16_t* __restrict__ Wh, const uint16_t* __restrict__ Wl,
    const float* __restrict__ bias, float* __restrict__ xout, int do_relu)
{
    extern __shared__ char smem[];
    const int tid = threadIdx.x;
    const int n0 = blockIdx.x * 128, m0 = blockIdx.y * 128;
    float* biasS = (float*)(smem + SM_BIAS);
    if (tid < 128) biasS[tid] = bias[n0 + tid];
    __syncthreads();

    ZERO_C();
    auto aload = [&](int row, int kg) -> float4 {
        int r = m0 + row;
        if (r >= N_NODES) return make_float4(0.f, 0.f, 0.f, 0.f);
        return *(const float4*)(g_h + (size_t)r * DH + kg);
    };
    mainloop_mma<DH>(smem, Wh, Wl, n0, aload, C);

    const int lane = tid & 31, warp = tid >> 5;
    const int wm = warp & 3, wn = warp >> 2;
#pragma unroll
    for (int i = 0; i < 2; ++i)
#pragma unroll
    for (int h = 0; h < 2; ++h) {
        int rl = 32 * wm + 16 * i + 8 * h + (lane >> 2);
        int r = m0 + rl;
        if (r >= N_NODES) continue;
        const float* xrow = xin + (size_t)r * DN + n0;
        float* orow = xout + (size_t)r * DN + n0;
#pragma unroll
        for (int j = 0; j < 8; ++j) {
            int cl = 64 * wn + 8 * j + 2 * (lane & 3);
            float2 xv = *(const float2*)(xrow + cl);
            float2 o;
            o.x = C[i][j][2 * h + 0] + biasS[cl + 0] + xv.x;
            o.y = C[i][j][2 * h + 1] + biasS[cl + 1] + xv.y;
            if (do_relu) { o.x = fmaxf(o.x, 0.f); o.y = fmaxf(o.y, 0.f); }
            *(float2*)(orow + cl) = o;
        }
    }
}

// ============================================================================
extern "C" void kernel_launch(void* const* d_in, const int* in_sizes, int n_in,
                              void* d_out, int out_size)
{
    (void)in_sizes; (void)n_in; (void)out_size;
    const float* node = (const float*)d_in[0];
    const float* edge = (const float*)d_in[1];
    const int*   eidx = (const int*)  d_in[2];
    const float* W1a  = (const float*)d_in[3];
    const float* b1a  = (const float*)d_in[4];
    const float* W1b  = (const float*)d_in[5];
    const float* b1b  = (const float*)d_in[6];
    const float* W2a  = (const float*)d_in[7];
    const float* b2a  = (const float*)d_in[8];
    const float* W2b  = (const float*)d_in[9];
    const float* b2b  = (const float*)d_in[10];
    float* out = (float*)d_out;

    const int* srcI = eidx;
    const int* dstI = eidx + N_EDGES;

    cudaFuncSetAttribute(g1_kernel, cudaFuncAttributeMaxDynamicSharedMemorySize, SMEM_TOTAL);
    cudaFuncSetAttribute(g2_kernel, cudaFuncAttributeMaxDynamicSharedMemorySize, SMEM_TOTAL);
    cudaFuncSetAttribute(g3_kernel, cudaFuncAttributeMaxDynamicSharedMemorySize, SMEM_TOTAL);
    cudaFuncSetAttribute(g4_kernel, cudaFuncAttributeMaxDynamicSharedMemorySize, SMEM_TOTAL);

    void* t;
    cudaGetSymbolAddress(&t, g_x);  float* p_gx = (float*)t;
    cudaGetSymbolAddress(&t, g_e);  float* p_ge = (float*)t;
    cudaGetSymbolAddress(&t, g_Wh); uint16_t* p_wh = (uint16_t*)t;
    cudaGetSymbolAddress(&t, g_Wl); uint16_t* p_wl = (uint16_t*)t;

    // pre-transpose + bf16-split all weights to [N][K]
    dim3 tb(32, 8);
    for (int l = 0; l < NLAYERS; ++l) {
        size_t base = (size_t)l * WT_LAYER;
        transpose_split_kernel<<<dim3(DH / 32, (2 * DN + DE) / 32), tb>>>(
            W1a + (size_t)l * (2 * DN + DE) * DH,
            p_wh + base + OFF_W1A, p_wl + base + OFF_W1A, 2 * DN + DE, DH);
        transpose_split_kernel<<<dim3((2 * DH + DE) / 32, DH / 32), tb>>>(
            W1b + (size_t)l * DH * (2 * DH + DE),
            p_wh + base + OFF_W1B, p_wl + base + OFF_W1B, DH, 2 * DH + DE);
        transpose_split_kernel<<<dim3(DH / 32, DH / 32), tb>>>(
            W2a + (size_t)l * DH * DH,
            p_wh + base + OFF_W2A, p_wl + base + OFF_W2A, DH, DH);
        transpose_split_kernel<<<dim3(DN / 32, DH / 32), tb>>>(
            W2b + (size_t)l * DH * DN,
            p_wh + base + OFF_W2B, p_wl + base + OFF_W2B, DH, DN);
    }

    zero_cnt_kernel<<<(N_NODES + 255) / 256, 256>>>();
    count_kernel<<<(N_EDGES + 255) / 256, 256>>>(dstI);

    const int MT_E = (N_EDGES + 127) / 128;  // 782
    const int MT_N = (N_NODES + 127) / 128;  // 157

    for (int l = 0; l < NLAYERS; ++l) {
        zero_agg_kernel<<<(N_NODES * DH / 4 + 255) / 256, 256>>>();

        const float* xin = (l == 0) ? node : p_gx;
        const float* ein = (l == 0) ? edge : p_ge;
        size_t base = (size_t)l * WT_LAYER;

        g1_kernel<<<dim3(DH / 128, MT_E), 256, SMEM_TOTAL>>>(
            xin, ein, srcI, dstI,
            p_wh + base + OFF_W1A, p_wl + base + OFF_W1A, b1a + (size_t)l * DH);

        float* eout = (l == NLAYERS - 1) ? (out + (size_t)N_NODES * DN) : p_ge;
        g2_kernel<<<dim3((2 * DH + DE) / 128, MT_E), 256, SMEM_TOTAL>>>(
            dstI, p_wh + base + OFF_W1B, p_wl + base + OFF_W1B,
            b1b + (size_t)l * (2 * DH + DE), eout);

        g3_kernel<<<dim3(DH / 128, MT_N), 256, SMEM_TOTAL>>>(
            p_wh + base + OFF_W2A, p_wl + base + OFF_W2A, b2a + (size_t)l * DH);

        float* xout = (l == NLAYERS - 1) ? out : p_gx;
        g4_kernel<<<dim3(DN / 128, MT_N), 256, SMEM_TOTAL>>>(
            xin, p_wh + base + OFF_W2B, p_wl + base + OFF_W2B,
            b2b + (size_t)l * DN, xout, (l < NLAYERS - 1) ? 1 : 0);
    }
}

// round 12
// speedup vs baseline: 2.3753x; 1.1482x over previous
#include <cuda_runtime.h>
#include <cuda_bf16.h>
#include <cstdint>

#define N_NODES 20000
#define N_EDGES 100000
#define DN 256
#define DE 256
#define DH 512
#define NLAYERS 2

// ---------------- scratch (device globals: allocation-free) ----------------
// all GEMM operands live as pre-split bf16 hi/lo pairs
__device__ __align__(16) uint16_t g_m1h[(size_t)N_EDGES * DH];
__device__ __align__(16) uint16_t g_m1l[(size_t)N_EDGES * DH];
__device__ __align__(16) uint16_t g_eh [(size_t)N_EDGES * DE];
__device__ __align__(16) uint16_t g_el [(size_t)N_EDGES * DE];
__device__ __align__(16) uint16_t g_xh [(size_t)N_NODES * DN];
__device__ __align__(16) uint16_t g_xl [(size_t)N_NODES * DN];
__device__ __align__(16) uint16_t g_aggh[(size_t)N_NODES * DH];
__device__ __align__(16) uint16_t g_aggl[(size_t)N_NODES * DH];
__device__ __align__(16) uint16_t g_hh [(size_t)N_NODES * DH];
__device__ __align__(16) uint16_t g_hl [(size_t)N_NODES * DH];
__device__ float g_x  [(size_t)N_NODES * DN];   // fp32 x for residual
__device__ float g_agg[(size_t)N_NODES * DH];   // fp32 atomics accumulator
__device__ float g_cnt[N_NODES];

// transposed + bf16-split weights [N][K] K-major, per layer
#define OFF_W1A 0
#define OFF_W1B (DH * (2 * DN + DE))
#define OFF_W2A (OFF_W1B + (2 * DH + DE) * DH)
#define OFF_W2B (OFF_W2A + DH * DH)
#define WT_LAYER (OFF_W2B + DH * DN)
__device__ __align__(16) uint16_t g_Wh[(size_t)NLAYERS * WT_LAYER];
__device__ __align__(16) uint16_t g_Wl[(size_t)NLAYERS * WT_LAYER];

// ---------------- helpers ----------------
__device__ __forceinline__ uint32_t smem_to_u32(const void* p) {
    uint32_t a;
    asm("{ .reg .u64 t; cvta.to.shared.u64 t, %1; cvt.u32.u64 %0, t; }"
        : "=r"(a) : "l"(p));
    return a;
}

// d.hi = bf16(hi), d.lo = bf16(lo)
__device__ __forceinline__ uint32_t cvt_bf16x2(float lo, float hi) {
    uint32_t r;
    asm("cvt.rn.bf16x2.f32 %0, %1, %2;" : "=r"(r) : "f"(hi), "f"(lo));
    return r;
}

// split (x, y) -> bf16x2 hi word + bf16x2 lo word
__device__ __forceinline__ void split2(float x, float y, uint32_t& hi, uint32_t& lo) {
    hi = cvt_bf16x2(x, y);
    float rx = x - __uint_as_float(hi << 16);
    float ry = y - __uint_as_float(hi & 0xFFFF0000u);
    lo = cvt_bf16x2(rx, ry);
}

__device__ __forceinline__ void cp16(uint32_t dst, const void* src) {
    asm volatile("cp.async.ca.shared.global [%0], [%1], 16;"
                 :: "r"(dst), "l"(src) : "memory");
}
#define CP_COMMIT() asm volatile("cp.async.commit_group;" ::: "memory")
#define CP_WAIT1()  asm volatile("cp.async.wait_group 1;" ::: "memory")
#define CP_WAIT0()  asm volatile("cp.async.wait_group 0;" ::: "memory")

__device__ __forceinline__ void ldsm4(uint32_t addr, uint32_t* r) {
    asm volatile("ldmatrix.sync.aligned.m8n8.x4.shared.b16 {%0,%1,%2,%3}, [%4];"
                 : "=r"(r[0]), "=r"(r[1]), "=r"(r[2]), "=r"(r[3]) : "r"(addr));
}

__device__ __forceinline__ void mma_bf16(float* c, const uint32_t* a,
                                         uint32_t b0, uint32_t b1) {
    asm volatile("mma.sync.aligned.m16n8k16.row.col.f32.bf16.bf16.f32 "
                 "{%0,%1,%2,%3}, {%4,%5,%6,%7}, {%8,%9}, {%0,%1,%2,%3};"
                 : "+f"(c[0]), "+f"(c[1]), "+f"(c[2]), "+f"(c[3])
                 : "r"(a[0]), "r"(a[1]), "r"(a[2]), "r"(a[3]), "r"(b0), "r"(b1));
}

__device__ __forceinline__ void red_add_v2(float* p, float x, float y) {
    asm volatile("red.global.add.v2.f32 [%0], {%1, %2};"
                 :: "l"(p), "f"(x), "f"(y) : "memory");
}

// ---------------- dynamic smem layout ----------------
#define SM_BIAS   0       // 128 floats
#define SM_DST    512     // 128 ints
#define SM_SRC    1024
#define SM_TILES  2048
#define PITCH     80                    // 64B bf16 row + 16B pad (ldmatrix conflict-free)
#define TILE_B    (128 * PITCH)         // 10240
#define STAGE_B   (4 * TILE_B)          // Ah Al Bh Bl
#define SMEM_TOTAL (SM_TILES + 2 * STAGE_B)  // 83968

// ---------------- utility kernels ----------------
__global__ void zero_cnt_kernel() {
    int i = blockIdx.x * blockDim.x + threadIdx.x;
    if (i < N_NODES) g_cnt[i] = 0.f;
}
__global__ void zero_agg_kernel() {
    int i = blockIdx.x * blockDim.x + threadIdx.x;
    if (i < N_NODES * DH / 4)
        ((float4*)g_agg)[i] = make_float4(0.f, 0.f, 0.f, 0.f);
}
__global__ void count_kernel(const int* __restrict__ dstI) {
    int e = blockIdx.x * blockDim.x + threadIdx.x;
    if (e < N_EDGES) atomicAdd(&g_cnt[dstI[e]], 1.f);
}

// fp32 -> bf16 hi/lo (element pairs)
__global__ void split_f32_kernel(const float* __restrict__ src,
                                 uint16_t* __restrict__ dh,
                                 uint16_t* __restrict__ dl, int npairs) {
    int i = blockIdx.x * blockDim.x + threadIdx.x;
    if (i < npairs) {
        float2 v = ((const float2*)src)[i];
        uint32_t hi, lo;
        split2(v.x, v.y, hi, lo);
        ((uint32_t*)dh)[i] = hi;
        ((uint32_t*)dl)[i] = lo;
    }
}

// agg: normalize by 1/max(cnt,1) and split
__global__ void split_agg_kernel() {
    int i = blockIdx.x * blockDim.x + threadIdx.x;
    if (i < N_NODES * DH / 2) {
        int row = i >> 8;  // 256 pairs per row
        float s = 1.f / fmaxf(g_cnt[row], 1.f);
        float2 v = ((const float2*)g_agg)[i];
        uint32_t hi, lo;
        split2(v.x * s, v.y * s, hi, lo);
        ((uint32_t*)g_aggh)[i] = hi;
        ((uint32_t*)g_aggl)[i] = lo;
    }
}

// W [K][N] row-major -> Wh/Wl [N][K] bf16 hi/lo split
__global__ void transpose_split_kernel(const float* __restrict__ src,
                                       uint16_t* __restrict__ dh,
                                       uint16_t* __restrict__ dl,
                                       int K, int N) {
    __shared__ float t[32][33];
    int bx = blockIdx.x * 32, by = blockIdx.y * 32;
    int tx = threadIdx.x, ty = threadIdx.y;
#pragma unroll
    for (int j = 0; j < 32; j += 8) {
        int k = by + ty + j, n = bx + tx;
        t[ty + j][tx] = (k < K && n < N) ? src[(size_t)k * N + n] : 0.f;
    }
    __syncthreads();
#pragma unroll
    for (int j = 0; j < 32; j += 8) {
        int n = bx + ty + j, k = by + tx;
        if (n < N && k < K) {
            float f = t[tx][ty + j];
            __nv_bfloat16 h = __float2bfloat16(f);
            __nv_bfloat16 lo = __float2bfloat16(f - __bfloat162float(h));
            dh[(size_t)n * K + k] = __bfloat16_as_ushort(h);
            dl[(size_t)n * K + k] = __bfloat16_as_ushort(lo);
        }
    }
}

// ---------------- 3x-bf16 mma.sync mainloop, cp.async 2-stage ring ----------
// 128x128 CTA tile, BK=32, 8 warps (4M x 2N), warp tile 32x64.
// asrc(row, kg, hl) -> global src ptr for A hi (hl=0) / lo (hl=1), 16B aligned.
template <int KDIM, class AS>
__device__ __forceinline__ void mainloop_mma(
    char* smem, const uint16_t* __restrict__ Wh, const uint16_t* __restrict__ Wl,
    int n0, AS asrc, float C[2][8][4])
{
    const int tid = threadIdx.x;
    const int lane = tid & 31, warp = tid >> 5;
    const int wm = warp & 3, wn = warp >> 2;
    const uint32_t sb = smem_to_u32(smem);
    constexpr int NC = KDIM / 32;

    auto issue = [&](int c) {
        const int st = c & 1;
        const uint32_t base = sb + SM_TILES + st * STAGE_B;
#pragma unroll
        for (int halfp = 0; halfp < 2; ++halfp) {
            int id = tid + halfp * 256;
            int row = id >> 2, seg = id & 3;
            int kg = c * 32 + seg * 8;
            uint32_t off = (uint32_t)row * PITCH + seg * 16;
            cp16(base + off,              asrc(row, kg, 0));
            cp16(base + TILE_B + off,     asrc(row, kg, 1));
            size_t bo = (size_t)(n0 + row) * KDIM + kg;
            cp16(base + 2 * TILE_B + off, Wh + bo);
            cp16(base + 3 * TILE_B + off, Wl + bo);
        }
        CP_COMMIT();
    };

    issue(0);
    if (NC > 1) issue(1);

    const int lrow = lane & 15;
    const int lk = (lane >> 4) * 16;

    for (int c = 0; c < NC; ++c) {
        if (c + 1 < NC) CP_WAIT1(); else CP_WAIT0();
        __syncthreads();
        const int st = c & 1;
        const uint32_t sAh = sb + SM_TILES + st * STAGE_B;
        const uint32_t sAl = sAh + TILE_B;
        const uint32_t sBh = sAl + TILE_B;
        const uint32_t sBl = sBh + TILE_B;
#pragma unroll
        for (int ks = 0; ks < 2; ++ks) {
            uint32_t ah[2][4], al[2][4];
#pragma unroll
            for (int i = 0; i < 2; ++i) {
                uint32_t ao = (uint32_t)(32 * wm + 16 * i + lrow) * PITCH + ks * 32 + lk;
                ldsm4(sAh + ao, ah[i]);
                ldsm4(sAl + ao, al[i]);
            }
#pragma unroll
            for (int g = 0; g < 4; ++g) {
                uint32_t bo = (uint32_t)(64 * wn + 16 * g + lrow) * PITCH + ks * 32 + lk;
                uint32_t bh[4], bl[4];
                ldsm4(sBh + bo, bh);
                ldsm4(sBl + bo, bl);
#pragma unroll
                for (int i = 0; i < 2; ++i) {
                    mma_bf16(C[i][2 * g],     ah[i], bh[0], bh[2]);
                    mma_bf16(C[i][2 * g + 1], ah[i], bh[1], bh[3]);
                    mma_bf16(C[i][2 * g],     al[i], bh[0], bh[2]);
                    mma_bf16(C[i][2 * g + 1], al[i], bh[1], bh[3]);
                    mma_bf16(C[i][2 * g],     ah[i], bl[0], bl[2]);
                    mma_bf16(C[i][2 * g + 1], ah[i], bl[1], bl[3]);
                }
            }
        }
        __syncthreads();
        if (c + 2 < NC) issue(c + 2);
    }
}

#define ZERO_C() \
    float C[2][8][4]; \
    _Pragma("unroll") for (int i = 0; i < 2; ++i) \
    _Pragma("unroll") for (int j = 0; j < 8; ++j) \
    _Pragma("unroll") for (int q = 0; q < 4; ++q) C[i][j][q] = 0.f;

// ============================================================================
// GEMM1: m1 = relu([x[dst]|e|x[src]] @ W1a + b1a) -> split bf16 m1h/m1l
// ============================================================================
__global__ void __launch_bounds__(256, 1) g1_kernel(
    const int* __restrict__ srcI, const int* __restrict__ dstI,
    const uint16_t* __restrict__ Wh, const uint16_t* __restrict__ Wl,
    const float* __restrict__ bias)
{
    extern __shared__ char smem[];
    const int tid = threadIdx.x;
    const int n0 = blockIdx.x * 128, m0 = blockIdx.y * 128;
    float* biasS = (float*)(smem + SM_BIAS);
    int* sDst = (int*)(smem + SM_DST);
    int* sSrc = (int*)(smem + SM_SRC);
    if (tid < 128) {
        biasS[tid] = bias[n0 + tid];
        int r = min(m0 + tid, N_EDGES - 1);
        sDst[tid] = dstI[r];
        sSrc[tid] = srcI[r];
    }
    __syncthreads();

    ZERO_C();
    auto asrc = [&](int row, int kg, int hl) -> const uint16_t* {
        int r = min(m0 + row, N_EDGES - 1);
        if (kg < DN)
            return (hl ? g_xl : g_xh) + (size_t)sDst[row] * DN + kg;
        if (kg < DN + DE)
            return (hl ? g_el : g_eh) + (size_t)r * DE + (kg - DN);
        return (hl ? g_xl : g_xh) + (size_t)sSrc[row] * DN + (kg - DN - DE);
    };
    mainloop_mma<2 * DN + DE>(smem, Wh, Wl, n0, asrc, C);

    const int lane = tid & 31, warp = tid >> 5;
    const int wm = warp & 3, wn = warp >> 2;
#pragma unroll
    for (int i = 0; i < 2; ++i)
#pragma unroll
    for (int h = 0; h < 2; ++h) {
        int rl = 32 * wm + 16 * i + 8 * h + (lane >> 2);
        int r = m0 + rl;
        if (r >= N_EDGES) continue;
#pragma unroll
        for (int j = 0; j < 8; ++j) {
            int cl = 64 * wn + 8 * j + 2 * (lane & 3);
            float ox = fmaxf(C[i][j][2 * h + 0] + biasS[cl + 0], 0.f);
            float oy = fmaxf(C[i][j][2 * h + 1] + biasS[cl + 1], 0.f);
            uint32_t hi, lo;
            split2(ox, oy, hi, lo);
            size_t o2 = ((size_t)r * DH + n0 + cl) >> 1;
            ((uint32_t*)g_m1h)[o2] = hi;
            ((uint32_t*)g_m1l)[o2] = lo;
        }
    }
}

// ============================================================================
// GEMM2: relu(m1 @ W1b + b1b)   (E x 512)@(512 x 1280)
// cols [0,512)+[768,1280) -> red.v2 into g_agg[dst]; [512,768) -> new_e
// ============================================================================
__global__ void __launch_bounds__(256, 1) g2_kernel(
    const int* __restrict__ dstI,
    const uint16_t* __restrict__ Wh, const uint16_t* __restrict__ Wl,
    const float* __restrict__ bias, float* __restrict__ eoutF, int last)
{
    extern __shared__ char smem[];
    const int tid = threadIdx.x;
    const int n0 = blockIdx.x * 128, m0 = blockIdx.y * 128;
    float* biasS = (float*)(smem + SM_BIAS);
    int* sDst = (int*)(smem + SM_DST);
    if (tid < 128) {
        biasS[tid] = bias[n0 + tid];
        sDst[tid] = dstI[min(m0 + tid, N_EDGES - 1)];
    }
    __syncthreads();

    ZERO_C();
    auto asrc = [&](int row, int kg, int hl) -> const uint16_t* {
        size_t r = (size_t)min(m0 + row, N_EDGES - 1);
        return (hl ? g_m1l : g_m1h) + r * DH + kg;
    };
    mainloop_mma<DH>(smem, Wh, Wl, n0, asrc, C);

    const int lane = tid & 31, warp = tid >> 5;
    const int wm = warp & 3, wn = warp >> 2;
    const int mode = (n0 < DH) ? 0 : ((n0 < DH + DE) ? 1 : 2);
    const int aggc0 = (mode == 2) ? (n0 - DH - DE) : n0;
#pragma unroll
    for (int i = 0; i < 2; ++i)
#pragma unroll
    for (int h = 0; h < 2; ++h) {
        int rl = 32 * wm + 16 * i + 8 * h + (lane >> 2);
        int r = m0 + rl;
        if (r >= N_EDGES) continue;
        int dn = sDst[rl];
#pragma unroll
        for (int j = 0; j < 8; ++j) {
            int cl = 64 * wn + 8 * j + 2 * (lane & 3);
            float ox = fmaxf(C[i][j][2 * h + 0] + biasS[cl + 0], 0.f);
            float oy = fmaxf(C[i][j][2 * h + 1] + biasS[cl + 1], 0.f);
            if (mode == 1) {
                size_t eoff = (size_t)r * DE + (n0 - DH) + cl;
                if (last) {
                    *(float2*)(eoutF + eoff) = make_float2(ox, oy);
                } else {
                    uint32_t hi, lo;
                    split2(ox, oy, hi, lo);
                    ((uint32_t*)g_eh)[eoff >> 1] = hi;
                    ((uint32_t*)g_el)[eoff >> 1] = lo;
                }
            } else {
                red_add_v2(g_agg + (size_t)dn * DH + aggc0 + cl, ox, oy);
            }
        }
    }
}

// ============================================================================
// GEMM3: h = relu(aggn @ W2a + b2a) -> split bf16 hh/hl   (N x 512)@(512 x 512)
// ============================================================================
__global__ void __launch_bounds__(256, 1) g3_kernel(
    const uint16_t* __restrict__ Wh, const uint16_t* __restrict__ Wl,
    const float* __restrict__ bias)
{
    extern __shared__ char smem[];
    const int tid = threadIdx.x;
    const int n0 = blockIdx.x * 128, m0 = blockIdx.y * 128;
    float* biasS = (float*)(smem + SM_BIAS);
    if (tid < 128) biasS[tid] = bias[n0 + tid];
    __syncthreads();

    ZERO_C();
    auto asrc = [&](int row, int kg, int hl) -> const uint16_t* {
        size_t r = (size_t)min(m0 + row, N_NODES - 1);
        return (hl ? g_aggl : g_aggh) + r * DH + kg;
    };
    mainloop_mma<DH>(smem, Wh, Wl, n0, asrc, C);

    const int lane = tid & 31, warp = tid >> 5;
    const int wm = warp & 3, wn = warp >> 2;
#pragma unroll
    for (int i = 0; i < 2; ++i)
#pragma unroll
    for (int h = 0; h < 2; ++h) {
        int rl = 32 * wm + 16 * i + 8 * h + (lane >> 2);
        int r = m0 + rl;
        if (r >= N_NODES) continue;
#pragma unroll
        for (int j = 0; j < 8; ++j) {
            int cl = 64 * wn + 8 * j + 2 * (lane & 3);
            float ox = fmaxf(C[i][j][2 * h + 0] + biasS[cl + 0], 0.f);
            float oy = fmaxf(C[i][j][2 * h + 1] + biasS[cl + 1], 0.f);
            uint32_t hi, lo;
            split2(ox, oy, hi, lo);
            size_t o2 = ((size_t)r * DH + n0 + cl) >> 1;
            ((uint32_t*)g_hh)[o2] = hi;
            ((uint32_t*)g_hl)[o2] = lo;
        }
    }
}

// ============================================================================
// GEMM4: new_x = x + (h @ W2b + b2b)  [+relu, + split for next layer]
// ============================================================================
__global__ void __launch_bounds__(256, 1) g4_kernel(
    const float* __restrict__ xin,
    const uint16_t* __restrict__ Wh, const uint16_t* __restrict__ Wl,
    const float* __restrict__ bias, float* __restrict__ xoutF, int last)
{
    extern __shared__ char smem[];
    const int tid = threadIdx.x;
    const int n0 = blockIdx.x * 128, m0 = blockIdx.y * 128;
    float* biasS = (float*)(smem + SM_BIAS);
    if (tid < 128) biasS[tid] = bias[n0 + tid];
    __syncthreads();

    ZERO_C();
    auto asrc = [&](int row, int kg, int hl) -> const uint16_t* {
        size_t r = (size_t)min(m0 + row, N_NODES - 1);
        return (hl ? g_hl : g_hh) + r * DH + kg;
    };
    mainloop_mma<DH>(smem, Wh, Wl, n0, asrc, C);

    const int lane = tid & 31, warp = tid >> 5;
    const int wm = warp & 3, wn = warp >> 2;
#pragma unroll
    for (int i = 0; i < 2; ++i)
#pragma unroll
    for (int h = 0; h < 2; ++h) {
        int rl = 32 * wm + 16 * i + 8 * h + (lane >> 2);
        int r = m0 + rl;
        if (r >= N_NODES) continue;
        const float* xrow = xin + (size_t)r * DN + n0;
#pragma unroll
        for (int j = 0; j < 8; ++j) {
            int cl = 64 * wn + 8 * j + 2 * (lane & 3);
            float2 xv = *(const float2*)(xrow + cl);
            float ox = C[i][j][2 * h + 0] + biasS[cl + 0] + xv.x;
            float oy = C[i][j][2 * h + 1] + biasS[cl + 1] + xv.y;
            size_t xoff = (size_t)r * DN + n0 + cl;
            if (last) {
                *(float2*)(xoutF + xoff) = make_float2(ox, oy);
            } else {
                ox = fmaxf(ox, 0.f); oy = fmaxf(oy, 0.f);
                *(float2*)(xoutF + xoff) = make_float2(ox, oy);
                uint32_t hi, lo;
                split2(ox, oy, hi, lo);
                ((uint32_t*)g_xh)[xoff >> 1] = hi;
                ((uint32_t*)g_xl)[xoff >> 1] = lo;
            }
        }
    }
}

// ============================================================================
extern "C" void kernel_launch(void* const* d_in, const int* in_sizes, int n_in,
                              void* d_out, int out_size)
{
    (void)in_sizes; (void)n_in; (void)out_size;
    const float* node = (const float*)d_in[0];
    const float* edge = (const float*)d_in[1];
    const int*   eidx = (const int*)  d_in[2];
    const float* W1a  = (const float*)d_in[3];
    const float* b1a  = (const float*)d_in[4];
    const float* W1b  = (const float*)d_in[5];
    const float* b1b  = (const float*)d_in[6];
    const float* W2a  = (const float*)d_in[7];
    const float* b2a  = (const float*)d_in[8];
    const float* W2b  = (const float*)d_in[9];
    const float* b2b  = (const float*)d_in[10];
    float* out = (float*)d_out;

    const int* srcI = eidx;
    const int* dstI = eidx + N_EDGES;

    cudaFuncSetAttribute(g1_kernel, cudaFuncAttributeMaxDynamicSharedMemorySize, SMEM_TOTAL);
    cudaFuncSetAttribute(g2_kernel, cudaFuncAttributeMaxDynamicSharedMemorySize, SMEM_TOTAL);
    cudaFuncSetAttribute(g3_kernel, cudaFuncAttributeMaxDynamicSharedMemorySize, SMEM_TOTAL);
    cudaFuncSetAttribute(g4_kernel, cudaFuncAttributeMaxDynamicSharedMemorySize, SMEM_TOTAL);

    void* t;
    cudaGetSymbolAddress(&t, g_x);  float* p_gx = (float*)t;
    cudaGetSymbolAddress(&t, g_xh); uint16_t* p_xh = (uint16_t*)t;
    cudaGetSymbolAddress(&t, g_xl); uint16_t* p_xl = (uint16_t*)t;
    cudaGetSymbolAddress(&t, g_eh); uint16_t* p_eh = (uint16_t*)t;
    cudaGetSymbolAddress(&t, g_el); uint16_t* p_el = (uint16_t*)t;
    cudaGetSymbolAddress(&t, g_Wh); uint16_t* p_wh = (uint16_t*)t;
    cudaGetSymbolAddress(&t, g_Wl); uint16_t* p_wl = (uint16_t*)t;

    // one-time splits of the inputs
    {
        int np = N_NODES * DN / 2;
        split_f32_kernel<<<(np + 255) / 256, 256>>>(node, p_xh, p_xl, np);
        np = N_EDGES * DE / 2;
        split_f32_kernel<<<(np + 255) / 256, 256>>>(edge, p_eh, p_el, np);
    }

    // pre-transpose + bf16-split all weights to [N][K]
    dim3 tb(32, 8);
    for (int l = 0; l < NLAYERS; ++l) {
        size_t base = (size_t)l * WT_LAYER;
        transpose_split_kernel<<<dim3(DH / 32, (2 * DN + DE) / 32), tb>>>(
            W1a + (size_t)l * (2 * DN + DE) * DH,
            p_wh + base + OFF_W1A, p_wl + base + OFF_W1A, 2 * DN + DE, DH);
        transpose_split_kernel<<<dim3((2 * DH + DE) / 32, DH / 32), tb>>>(
            W1b + (size_t)l * DH * (2 * DH + DE),
            p_wh + base + OFF_W1B, p_wl + base + OFF_W1B, DH, 2 * DH + DE);
        transpose_split_kernel<<<dim3(DH / 32, DH / 32), tb>>>(
            W2a + (size_t)l * DH * DH,
            p_wh + base + OFF_W2A, p_wl + base + OFF_W2A, DH, DH);
        transpose_split_kernel<<<dim3(DN / 32, DH / 32), tb>>>(
            W2b + (size_t)l * DH * DN,
            p_wh + base + OFF_W2B, p_wl + base + OFF_W2B, DH, DN);
    }

    zero_cnt_kernel<<<(N_NODES + 255) / 256, 256>>>();
    count_kernel<<<(N_EDGES + 255) / 256, 256>>>(dstI);

    const int MT_E = (N_EDGES + 127) / 128;  // 782
    const int MT_N = (N_NODES + 127) / 128;  // 157

    for (int l = 0; l < NLAYERS; ++l) {
        const int last = (l == NLAYERS - 1) ? 1 : 0;
        size_t base = (size_t)l * WT_LAYER;

        zero_agg_kernel<<<(N_NODES * DH / 4 + 255) / 256, 256>>>();

        g1_kernel<<<dim3(DH / 128, MT_E), 256, SMEM_TOTAL>>>(
            srcI, dstI, p_wh + base + OFF_W1A, p_wl + base + OFF_W1A,
            b1a + (size_t)l * DH);

        g2_kernel<<<dim3((2 * DH + DE) / 128, MT_E), 256, SMEM_TOTAL>>>(
            dstI, p_wh + base + OFF_W1B, p_wl + base + OFF_W1B,
            b1b + (size_t)l * (2 * DH + DE),
            last ? (out + (size_t)N_NODES * DN) : nullptr, last);

        split_agg_kernel<<<(N_NODES * DH / 2 + 255) / 256, 256>>>();

        g3_kernel<<<dim3(DH / 128, MT_N), 256, SMEM_TOTAL>>>(
            p_wh + base + OFF_W2A, p_wl + base + OFF_W2A, b2a + (size_t)l * DH);

        const float* xin = (l == 0) ? node : p_gx;
        g4_kernel<<<dim3(DN / 128, MT_N), 256, SMEM_TOTAL>>>(
            xin, p_wh + base + OFF_W2B, p_wl + base + OFF_W2B,
            b2b + (size_t)l * DN, last ? out : p_gx, last);
    }
}

// round 13
// speedup vs baseline: 3.5749x; 1.5050x over previous
#include <cuda_runtime.h>
#include <cuda_fp16.h>
#include <cstdint>

#define N_NODES 20000
#define N_EDGES 100000
#define DN 256
#define DE 256
#define DH 512
#define NLAYERS 2

// ---------------- scratch (device globals: allocation-free) ----------------
// A-side operands: single fp16. B-side (weights): fp16 hi/lo split.
__device__ __align__(16) uint16_t g_m1f [(size_t)N_EDGES * DH];
__device__ __align__(16) uint16_t g_ef  [(size_t)N_EDGES * DE];
__device__ __align__(16) uint16_t g_xf  [(size_t)N_NODES * DN];
__device__ __align__(16) uint16_t g_aggf[(size_t)N_NODES * DH];
__device__ __align__(16) uint16_t g_hf  [(size_t)N_NODES * DH];
__device__ float g_x  [(size_t)N_NODES * DN];   // fp32 x for residual
__device__ float g_agg[(size_t)N_NODES * DH];   // fp32 atomics accumulator
__device__ float g_cnt[N_NODES];

// transposed + fp16-split weights [N][K] K-major, per layer
#define OFF_W1A 0
#define OFF_W1B (DH * (2 * DN + DE))
#define OFF_W2A (OFF_W1B + (2 * DH + DE) * DH)
#define OFF_W2B (OFF_W2A + DH * DH)
#define WT_LAYER (OFF_W2B + DH * DN)
__device__ __align__(16) uint16_t g_Wh[(size_t)NLAYERS * WT_LAYER];
__device__ __align__(16) uint16_t g_Wl[(size_t)NLAYERS * WT_LAYER];

// ---------------- helpers ----------------
__device__ __forceinline__ uint32_t smem_to_u32(const void* p) {
    uint32_t a;
    asm("{ .reg .u64 t; cvta.to.shared.u64 t, %1; cvt.u32.u64 %0, t; }"
        : "=r"(a) : "l"(p));
    return a;
}

// pack (x, y) -> fp16x2, x in low half
__device__ __forceinline__ uint32_t f16x2(float x, float y) {
    uint32_t r;
    asm("cvt.rn.f16x2.f32 %0, %1, %2;" : "=r"(r) : "f"(y), "f"(x));
    return r;
}

__device__ __forceinline__ void cp16(uint32_t dst, const void* src) {
    asm volatile("cp.async.ca.shared.global [%0], [%1], 16;"
                 :: "r"(dst), "l"(src) : "memory");
}
#define CP_COMMIT() asm volatile("cp.async.commit_group;" ::: "memory")
#define CP_WAIT1()  asm volatile("cp.async.wait_group 1;" ::: "memory")
#define CP_WAIT0()  asm volatile("cp.async.wait_group 0;" ::: "memory")

__device__ __forceinline__ void ldsm4(uint32_t addr, uint32_t* r) {
    asm volatile("ldmatrix.sync.aligned.m8n8.x4.shared.b16 {%0,%1,%2,%3}, [%4];"
                 : "=r"(r[0]), "=r"(r[1]), "=r"(r[2]), "=r"(r[3]) : "r"(addr));
}

__device__ __forceinline__ void mma_f16(float* c, const uint32_t* a,
                                        uint32_t b0, uint32_t b1) {
    asm volatile("mma.sync.aligned.m16n8k16.row.col.f32.f16.f16.f32 "
                 "{%0,%1,%2,%3}, {%4,%5,%6,%7}, {%8,%9}, {%0,%1,%2,%3};"
                 : "+f"(c[0]), "+f"(c[1]), "+f"(c[2]), "+f"(c[3])
                 : "r"(a[0]), "r"(a[1]), "r"(a[2]), "r"(a[3]), "r"(b0), "r"(b1));
}

__device__ __forceinline__ void red_add_v2(float* p, float x, float y) {
    asm volatile("red.global.add.v2.f32 [%0], {%1, %2};"
                 :: "l"(p), "f"(x), "f"(y) : "memory");
}

// ---------------- dynamic smem layout ----------------
#define SM_BIAS   0       // 128 floats
#define SM_DST    512     // 128 ints
#define SM_SRC    1024
#define SM_TILES  2048
#define PITCH     80                    // 64B fp16 row + 16B pad (ldmatrix conflict-free)
#define TILE_B    (128 * PITCH)         // 10240
#define STAGE_B   (3 * TILE_B)          // A, Bh, Bl
#define SMEM_TOTAL (SM_TILES + 2 * STAGE_B)  // 63488 -> 2 CTAs/SM

// ---------------- utility kernels ----------------
__global__ void zero_cnt_kernel() {
    int i = blockIdx.x * blockDim.x + threadIdx.x;
    if (i < N_NODES) g_cnt[i] = 0.f;
}
__global__ void zero_agg_kernel() {
    int i = blockIdx.x * blockDim.x + threadIdx.x;
    if (i < N_NODES * DH / 4)
        ((float4*)g_agg)[i] = make_float4(0.f, 0.f, 0.f, 0.f);
}
__global__ void count_kernel(const int* __restrict__ dstI) {
    int e = blockIdx.x * blockDim.x + threadIdx.x;
    if (e < N_EDGES) atomicAdd(&g_cnt[dstI[e]], 1.f);
}

// fp32 -> fp16 (element pairs)
__global__ void round_f16_kernel(const float* __restrict__ src,
                                 uint16_t* __restrict__ dst, int npairs) {
    int i = blockIdx.x * blockDim.x + threadIdx.x;
    if (i < npairs) {
        float2 v = ((const float2*)src)[i];
        ((uint32_t*)dst)[i] = f16x2(v.x, v.y);
    }
}

// agg: normalize by 1/max(cnt,1), round to fp16
__global__ void norm_agg_kernel() {
    int i = blockIdx.x * blockDim.x + threadIdx.x;
    if (i < N_NODES * DH / 2) {
        int row = i >> 8;  // 256 pairs per row
        float s = 1.f / fmaxf(g_cnt[row], 1.f);
        float2 v = ((const float2*)g_agg)[i];
        ((uint32_t*)g_aggf)[i] = f16x2(v.x * s, v.y * s);
    }
}

// W [K][N] row-major -> Wh/Wl [N][K] fp16 hi/lo split
__global__ void transpose_split_kernel(const float* __restrict__ src,
                                       uint16_t* __restrict__ dh,
                                       uint16_t* __restrict__ dl,
                                       int K, int N) {
    __shared__ float t[32][33];
    int bx = blockIdx.x * 32, by = blockIdx.y * 32;
    int tx = threadIdx.x, ty = threadIdx.y;
#pragma unroll
    for (int j = 0; j < 32; j += 8) {
        int k = by + ty + j, n = bx + tx;
        t[ty + j][tx] = (k < K && n < N) ? src[(size_t)k * N + n] : 0.f;
    }
    __syncthreads();
#pragma unroll
    for (int j = 0; j < 32; j += 8) {
        int n = bx + ty + j, k = by + tx;
        if (n < N && k < K) {
            float f = t[tx][ty + j];
            __half h = __float2half_rn(f);
            __half lo = __float2half_rn(f - __half2float(h));
            dh[(size_t)n * K + k] = __half_as_ushort(h);
            dl[(size_t)n * K + k] = __half_as_ushort(lo);
        }
    }
}

// ---------------- 2x-fp16 mma.sync mainloop, cp.async 2-stage ring ----------
// 128x128 CTA tile, BK=32, 8 warps (4M x 2N), warp tile 32x64.
// A single fp16, B = Wh + Wl split. D = A*Bh + A*Bl.
template <int KDIM, class AS>
__device__ __forceinline__ void mainloop_mma(
    char* smem, const uint16_t* __restrict__ Wh, const uint16_t* __restrict__ Wl,
    int n0, AS asrc, float C[2][8][4])
{
    const int tid = threadIdx.x;
    const int lane = tid & 31, warp = tid >> 5;
    const int wm = warp & 3, wn = warp >> 2;
    const uint32_t sb = smem_to_u32(smem);
    constexpr int NC = KDIM / 32;

    auto issue = [&](int c) {
        const int st = c & 1;
        const uint32_t base = sb + SM_TILES + st * STAGE_B;
#pragma unroll
        for (int halfp = 0; halfp < 2; ++halfp) {
            int id = tid + halfp * 256;
            int row = id >> 2, seg = id & 3;
            int kg = c * 32 + seg * 8;
            uint32_t off = (uint32_t)row * PITCH + seg * 16;
            cp16(base + off, asrc(row, kg));
            size_t bo = (size_t)(n0 + row) * KDIM + kg;
            cp16(base + TILE_B + off,     Wh + bo);
            cp16(base + 2 * TILE_B + off, Wl + bo);
        }
        CP_COMMIT();
    };

    issue(0);
    if (NC > 1) issue(1);

    const int lrow = lane & 15;
    const int lk = (lane >> 4) * 16;

    for (int c = 0; c < NC; ++c) {
        if (c + 1 < NC) CP_WAIT1(); else CP_WAIT0();
        __syncthreads();
        const int st = c & 1;
        const uint32_t sA  = sb + SM_TILES + st * STAGE_B;
        const uint32_t sBh = sA + TILE_B;
        const uint32_t sBl = sBh + TILE_B;
#pragma unroll
        for (int ks = 0; ks < 2; ++ks) {
            uint32_t a[2][4];
#pragma unroll
            for (int i = 0; i < 2; ++i) {
                uint32_t ao = (uint32_t)(32 * wm + 16 * i + lrow) * PITCH + ks * 32 + lk;
                ldsm4(sA + ao, a[i]);
            }
#pragma unroll
            for (int g = 0; g < 4; ++g) {
                uint32_t bo = (uint32_t)(64 * wn + 16 * g + lrow) * PITCH + ks * 32 + lk;
                uint32_t bh[4], bl[4];
                ldsm4(sBh + bo, bh);
                ldsm4(sBl + bo, bl);
#pragma unroll
                for (int i = 0; i < 2; ++i) {
                    mma_f16(C[i][2 * g],     a[i], bh[0], bh[2]);
                    mma_f16(C[i][2 * g + 1], a[i], bh[1], bh[3]);
                    mma_f16(C[i][2 * g],     a[i], bl[0], bl[2]);
                    mma_f16(C[i][2 * g + 1], a[i], bl[1], bl[3]);
                }
            }
        }
        __syncthreads();
        if (c + 2 < NC) issue(c + 2);
    }
}

#define ZERO_C() \
    float C[2][8][4]; \
    _Pragma("unroll") for (int i = 0; i < 2; ++i) \
    _Pragma("unroll") for (int j = 0; j < 8; ++j) \
    _Pragma("unroll") for (int q = 0; q < 4; ++q) C[i][j][q] = 0.f;

// ============================================================================
// GEMM1: m1 = relu([x[dst]|e|x[src]] @ W1a + b1a) -> fp16 m1f
// ============================================================================
__global__ void __launch_bounds__(256, 2) g1_kernel(
    const int* __restrict__ srcI, const int* __restrict__ dstI,
    const uint16_t* __restrict__ Wh, const uint16_t* __restrict__ Wl,
    const float* __restrict__ bias)
{
    extern __shared__ char smem[];
    const int tid = threadIdx.x;
    const int n0 = blockIdx.x * 128, m0 = blockIdx.y * 128;
    float* biasS = (float*)(smem + SM_BIAS);
    int* sDst = (int*)(smem + SM_DST);
    int* sSrc = (int*)(smem + SM_SRC);
    if (tid < 128) {
        biasS[tid] = bias[n0 + tid];
        int r = min(m0 + tid, N_EDGES - 1);
        sDst[tid] = dstI[r];
        sSrc[tid] = srcI[r];
    }
    __syncthreads();

    ZERO_C();
    auto asrc = [&](int row, int kg) -> const uint16_t* {
        int r = min(m0 + row, N_EDGES - 1);
        if (kg < DN)           return g_xf + (size_t)sDst[row] * DN + kg;
        if (kg < DN + DE)      return g_ef + (size_t)r * DE + (kg - DN);
        return g_xf + (size_t)sSrc[row] * DN + (kg - DN - DE);
    };
    mainloop_mma<2 * DN + DE>(smem, Wh, Wl, n0, asrc, C);

    const int lane = tid & 31, warp = tid >> 5;
    const int wm = warp & 3, wn = warp >> 2;
#pragma unroll
    for (int i = 0; i < 2; ++i)
#pragma unroll
    for (int h = 0; h < 2; ++h) {
        int rl = 32 * wm + 16 * i + 8 * h + (lane >> 2);
        int r = m0 + rl;
        if (r >= N_EDGES) continue;
#pragma unroll
        for (int j = 0; j < 8; ++j) {
            int cl = 64 * wn + 8 * j + 2 * (lane & 3);
            float ox = fmaxf(C[i][j][2 * h + 0] + biasS[cl + 0], 0.f);
            float oy = fmaxf(C[i][j][2 * h + 1] + biasS[cl + 1], 0.f);
            ((uint32_t*)g_m1f)[((size_t)r * DH + n0 + cl) >> 1] = f16x2(ox, oy);
        }
    }
}

// ============================================================================
// GEMM2: relu(m1 @ W1b + b1b)   (E x 512)@(512 x 1280)
// cols [0,512)+[768,1280) -> red.v2 into g_agg[dst]; [512,768) -> new_e
// ============================================================================
__global__ void __launch_bounds__(256, 2) g2_kernel(
    const int* __restrict__ dstI,
    const uint16_t* __restrict__ Wh, const uint16_t* __restrict__ Wl,
    const float* __restrict__ bias, float* __restrict__ eoutF, int last)
{
    extern __shared__ char smem[];
    const int tid = threadIdx.x;
    const int n0 = blockIdx.x * 128, m0 = blockIdx.y * 128;
    float* biasS = (float*)(smem + SM_BIAS);
    int* sDst = (int*)(smem + SM_DST);
    if (tid < 128) {
        biasS[tid] = bias[n0 + tid];
        sDst[tid] = dstI[min(m0 + tid, N_EDGES - 1)];
    }
    __syncthreads();

    ZERO_C();
    auto asrc = [&](int row, int kg) -> const uint16_t* {
        size_t r = (size_t)min(m0 + row, N_EDGES - 1);
        return g_m1f + r * DH + kg;
    };
    mainloop_mma<DH>(smem, Wh, Wl, n0, asrc, C);

    const int lane = tid & 31, warp = tid >> 5;
    const int wm = warp & 3, wn = warp >> 2;
    const int mode = (n0 < DH) ? 0 : ((n0 < DH + DE) ? 1 : 2);
    const int aggc0 = (mode == 2) ? (n0 - DH - DE) : n0;
#pragma unroll
    for (int i = 0; i < 2; ++i)
#pragma unroll
    for (int h = 0; h < 2; ++h) {
        int rl = 32 * wm + 16 * i + 8 * h + (lane >> 2);
        int r = m0 + rl;
        if (r >= N_EDGES) continue;
        int dn = sDst[rl];
#pragma unroll
        for (int j = 0; j < 8; ++j) {
            int cl = 64 * wn + 8 * j + 2 * (lane & 3);
            float ox = fmaxf(C[i][j][2 * h + 0] + biasS[cl + 0], 0.f);
            float oy = fmaxf(C[i][j][2 * h + 1] + biasS[cl + 1], 0.f);
            if (mode == 1) {
                size_t eoff = (size_t)r * DE + (n0 - DH) + cl;
                if (last) *(float2*)(eoutF + eoff) = make_float2(ox, oy);
                else      ((uint32_t*)g_ef)[eoff >> 1] = f16x2(ox, oy);
            } else {
                red_add_v2(g_agg + (size_t)dn * DH + aggc0 + cl, ox, oy);
            }
        }
    }
}

// ============================================================================
// GEMM3: h = relu(aggn @ W2a + b2a) -> fp16 hf   (N x 512)@(512 x 512)
// ============================================================================
__global__ void __launch_bounds__(256, 2) g3_kernel(
    const uint16_t* __restrict__ Wh, const uint16_t* __restrict__ Wl,
    const float* __restrict__ bias)
{
    extern __shared__ char smem[];
    const int tid = threadIdx.x;
    const int n0 = blockIdx.x * 128, m0 = blockIdx.y * 128;
    float* biasS = (float*)(smem + SM_BIAS);
    if (tid < 128) biasS[tid] = bias[n0 + tid];
    __syncthreads();

    ZERO_C();
    auto asrc = [&](int row, int kg) -> const uint16_t* {
        size_t r = (size_t)min(m0 + row, N_NODES - 1);
        return g_aggf + r * DH + kg;
    };
    mainloop_mma<DH>(smem, Wh, Wl, n0, asrc, C);

    const int lane = tid & 31, warp = tid >> 5;
    const int wm = warp & 3, wn = warp >> 2;
#pragma unroll
    for (int i = 0; i < 2; ++i)
#pragma unroll
    for (int h = 0; h < 2; ++h) {
        int rl = 32 * wm + 16 * i + 8 * h + (lane >> 2);
        int r = m0 + rl;
        if (r >= N_NODES) continue;
#pragma unroll
        for (int j = 0; j < 8; ++j) {
            int cl = 64 * wn + 8 * j + 2 * (lane & 3);
            float ox = fmaxf(C[i][j][2 * h + 0] + biasS[cl + 0], 0.f);
            float oy = fmaxf(C[i][j][2 * h + 1] + biasS[cl + 1], 0.f);
            ((uint32_t*)g_hf)[((size_t)r * DH + n0 + cl) >> 1] = f16x2(ox, oy);
        }
    }
}

// ============================================================================
// GEMM4: new_x = x + (h @ W2b + b2b)  [+relu, + fp16 copy for next layer]
// ============================================================================
__global__ void __launch_bounds__(256, 2) g4_kernel(
    const float* __restrict__ xin,
    const uint16_t* __restrict__ Wh, const uint16_t* __restrict__ Wl,
    const float* __restrict__ bias, float* __restrict__ xoutF, int last)
{
    extern __shared__ char smem[];
    const int tid = threadIdx.x;
    const int n0 = blockIdx.x * 128, m0 = blockIdx.y * 128;
    float* biasS = (float*)(smem + SM_BIAS);
    if (tid < 128) biasS[tid] = bias[n0 + tid];
    __syncthreads();

    ZERO_C();
    auto asrc = [&](int row, int kg) -> const uint16_t* {
        size_t r = (size_t)min(m0 + row, N_NODES - 1);
        return g_hf + r * DH + kg;
    };
    mainloop_mma<DH>(smem, Wh, Wl, n0, asrc, C);

    const int lane = tid & 31, warp = tid >> 5;
    const int wm = warp & 3, wn = warp >> 2;
#pragma unroll
    for (int i = 0; i < 2; ++i)
#pragma unroll
    for (int h = 0; h < 2; ++h) {
        int rl = 32 * wm + 16 * i + 8 * h + (lane >> 2);
        int r = m0 + rl;
        if (r >= N_NODES) continue;
        const float* xrow = xin + (size_t)r * DN + n0;
#pragma unroll
        for (int j = 0; j < 8; ++j) {
            int cl = 64 * wn + 8 * j + 2 * (lane & 3);
            float2 xv = *(const float2*)(xrow + cl);
            float ox = C[i][j][2 * h + 0] + biasS[cl + 0] + xv.x;
            float oy = C[i][j][2 * h + 1] + biasS[cl + 1] + xv.y;
            size_t xoff = (size_t)r * DN + n0 + cl;
            if (last) {
                *(float2*)(xoutF + xoff) = make_float2(ox, oy);
            } else {
                ox = fmaxf(ox, 0.f); oy = fmaxf(oy, 0.f);
                *(float2*)(xoutF + xoff) = make_float2(ox, oy);
                ((uint32_t*)g_xf)[xoff >> 1] = f16x2(ox, oy);
            }
        }
    }
}

// ============================================================================
extern "C" void kernel_launch(void* const* d_in, const int* in_sizes, int n_in,
                              void* d_out, int out_size)
{
    (void)in_sizes; (void)n_in; (void)out_size;
    const float* node = (const float*)d_in[0];
    const float* edge = (const float*)d_in[1];
    const int*   eidx = (const int*)  d_in[2];
    const float* W1a  = (const float*)d_in[3];
    const float* b1a  = (const float*)d_in[4];
    const float* W1b  = (const float*)d_in[5];
    const float* b1b  = (const float*)d_in[6];
    const float* W2a  = (const float*)d_in[7];
    const float* b2a  = (const float*)d_in[8];
    const float* W2b  = (const float*)d_in[9];
    const float* b2b  = (const float*)d_in[10];
    float* out = (float*)d_out;

    const int* srcI = eidx;
    const int* dstI = eidx + N_EDGES;

    cudaFuncSetAttribute(g1_kernel, cudaFuncAttributeMaxDynamicSharedMemorySize, SMEM_TOTAL);
    cudaFuncSetAttribute(g2_kernel, cudaFuncAttributeMaxDynamicSharedMemorySize, SMEM_TOTAL);
    cudaFuncSetAttribute(g3_kernel, cudaFuncAttributeMaxDynamicSharedMemorySize, SMEM_TOTAL);
    cudaFuncSetAttribute(g4_kernel, cudaFuncAttributeMaxDynamicSharedMemorySize, SMEM_TOTAL);

    void* t;
    cudaGetSymbolAddress(&t, g_x);  float* p_gx = (float*)t;
    cudaGetSymbolAddress(&t, g_xf); uint16_t* p_xf = (uint16_t*)t;
    cudaGetSymbolAddress(&t, g_ef); uint16_t* p_ef = (uint16_t*)t;
    cudaGetSymbolAddress(&t, g_Wh); uint16_t* p_wh = (uint16_t*)t;
    cudaGetSymbolAddress(&t, g_Wl); uint16_t* p_wl = (uint16_t*)t;

    // one-time rounding of the inputs to fp16
    {
        int np = N_NODES * DN / 2;
        round_f16_kernel<<<(np + 255) / 256, 256>>>(node, p_xf, np);
        np = N_EDGES * DE / 2;
        round_f16_kernel<<<(np + 255) / 256, 256>>>(edge, p_ef, np);
    }

    // pre-transpose + fp16-split all weights to [N][K]
    dim3 tb(32, 8);
    for (int l = 0; l < NLAYERS; ++l) {
        size_t base = (size_t)l * WT_LAYER;
        transpose_split_kernel<<<dim3(DH / 32, (2 * DN + DE) / 32), tb>>>(
            W1a + (size_t)l * (2 * DN + DE) * DH,
            p_wh + base + OFF_W1A, p_wl + base + OFF_W1A, 2 * DN + DE, DH);
        transpose_split_kernel<<<dim3((2 * DH + DE) / 32, DH / 32), tb>>>(
            W1b + (size_t)l * DH * (2 * DH + DE),
            p_wh + base + OFF_W1B, p_wl + base + OFF_W1B, DH, 2 * DH + DE);
        transpose_split_kernel<<<dim3(DH / 32, DH / 32), tb>>>(
            W2a + (size_t)l * DH * DH,
            p_wh + base + OFF_W2A, p_wl + base + OFF_W2A, DH, DH);
        transpose_split_kernel<<<dim3(DN / 32, DH / 32), tb>>>(
            W2b + (size_t)l * DH * DN,
            p_wh + base + OFF_W2B, p_wl + base + OFF_W2B, DH, DN);
    }

    zero_cnt_kernel<<<(N_NODES + 255) / 256, 256>>>();
    count_kernel<<<(N_EDGES + 255) / 256, 256>>>(dstI);

    const int MT_E = (N_EDGES + 127) / 128;  // 782
    const int MT_N = (N_NODES + 127) / 128;  // 157

    for (int l = 0; l < NLAYERS; ++l) {
        const int last = (l == NLAYERS - 1) ? 1 : 0;
        size_t base = (size_t)l * WT_LAYER;

        zero_agg_kernel<<<(N_NODES * DH / 4 + 255) / 256, 256>>>();

        g1_kernel<<<dim3(DH / 128, MT_E), 256, SMEM_TOTAL>>>(
            srcI, dstI, p_wh + base + OFF_W1A, p_wl + base + OFF_W1A,
            b1a + (size_t)l * DH);

        g2_kernel<<<dim3((2 * DH + DE) / 128, MT_E), 256, SMEM_TOTAL>>>(
            dstI, p_wh + base + OFF_W1B, p_wl + base + OFF_W1B,
            b1b + (size_t)l * (2 * DH + DE),
            last ? (out + (size_t)N_NODES * DN) : nullptr, last);

        norm_agg_kernel<<<(N_NODES * DH / 2 + 255) / 256, 256>>>();

        g3_kernel<<<dim3(DH / 128, MT_N), 256, SMEM_TOTAL>>>(
            p_wh + base + OFF_W2A, p_wl + base + OFF_W2A, b2a + (size_t)l * DH);

        const float* xin = (l == 0) ? node : p_gx;
        g4_kernel<<<dim3(DN / 128, MT_N), 256, SMEM_TOTAL>>>(
            xin, p_wh + base + OFF_W2B, p_wl + base + OFF_W2B,
            b2b + (size_t)l * DN, last ? out : p_gx, last);
    }
}

// round 14
// speedup vs baseline: 5.7405x; 1.6058x over previous
#include <cuda_runtime.h>
#include <cuda_fp16.h>
#include <cstdint>

#define N_NODES 20000
#define N_EDGES 100000
#define DN 256
#define DE 256
#define DH 512
#define NLAYERS 2

// ---------------- scratch (device globals: allocation-free) ----------------
// all GEMM operands single fp16
__device__ __align__(16) uint16_t g_m1f [(size_t)N_EDGES * DH];
__device__ __align__(16) uint16_t g_ef  [(size_t)N_EDGES * DE];
__device__ __align__(16) uint16_t g_xf  [(size_t)N_NODES * DN];
__device__ __align__(16) uint16_t g_aggf[(size_t)N_NODES * DH];
__device__ __align__(16) uint16_t g_hf  [(size_t)N_NODES * DH];
__device__ float g_x  [(size_t)N_NODES * DN];   // fp32 x for residual
__device__ float g_agg[(size_t)N_NODES * DH];   // fp32 atomics accumulator
__device__ float g_cnt[N_NODES];

// transposed fp16 weights [N][K] K-major, per layer
#define OFF_W1A 0
#define OFF_W1B (DH * (2 * DN + DE))
#define OFF_W2A (OFF_W1B + (2 * DH + DE) * DH)
#define OFF_W2B (OFF_W2A + DH * DH)
#define WT_LAYER (OFF_W2B + DH * DN)
__device__ __align__(16) uint16_t g_Wf[(size_t)NLAYERS * WT_LAYER];

// ---------------- helpers ----------------
__device__ __forceinline__ uint32_t smem_to_u32(const void* p) {
    uint32_t a;
    asm("{ .reg .u64 t; cvta.to.shared.u64 t, %1; cvt.u32.u64 %0, t; }"
        : "=r"(a) : "l"(p));
    return a;
}

// pack (x, y) -> fp16x2, x in low half
__device__ __forceinline__ uint32_t f16x2(float x, float y) {
    uint32_t r;
    asm("cvt.rn.f16x2.f32 %0, %1, %2;" : "=r"(r) : "f"(y), "f"(x));
    return r;
}

__device__ __forceinline__ void cp16(uint32_t dst, const void* src) {
    asm volatile("cp.async.ca.shared.global [%0], [%1], 16;"
                 :: "r"(dst), "l"(src) : "memory");
}
#define CP_COMMIT() asm volatile("cp.async.commit_group;" ::: "memory")
#define CP_WAIT2()  asm volatile("cp.async.wait_group 2;" ::: "memory")
#define CP_WAIT1()  asm volatile("cp.async.wait_group 1;" ::: "memory")
#define CP_WAIT0()  asm volatile("cp.async.wait_group 0;" ::: "memory")

__device__ __forceinline__ void ldsm4(uint32_t addr, uint32_t* r) {
    asm volatile("ldmatrix.sync.aligned.m8n8.x4.shared.b16 {%0,%1,%2,%3}, [%4];"
                 : "=r"(r[0]), "=r"(r[1]), "=r"(r[2]), "=r"(r[3]) : "r"(addr));
}

__device__ __forceinline__ void mma_f16(float* c, const uint32_t* a,
                                        uint32_t b0, uint32_t b1) {
    asm volatile("mma.sync.aligned.m16n8k16.row.col.f32.f16.f16.f32 "
                 "{%0,%1,%2,%3}, {%4,%5,%6,%7}, {%8,%9}, {%0,%1,%2,%3};"
                 : "+f"(c[0]), "+f"(c[1]), "+f"(c[2]), "+f"(c[3])
                 : "r"(a[0]), "r"(a[1]), "r"(a[2]), "r"(a[3]), "r"(b0), "r"(b1));
}

__device__ __forceinline__ void red_add_v2(float* p, float x, float y) {
    asm volatile("red.global.add.v2.f32 [%0], {%1, %2};"
                 :: "l"(p), "f"(x), "f"(y) : "memory");
}

// ---------------- dynamic smem layout ----------------
#define SM_BIAS   0       // 128 floats
#define SM_DST    512     // 128 ints
#define SM_SRC    1024
#define SM_TILES  2048
#define PITCH     80                    // 64B fp16 row + 16B pad (ldmatrix conflict-free)
#define TILE_B    (128 * PITCH)         // 10240
#define STAGE_B   (2 * TILE_B)          // A, B
#define NSTAGE    3
#define SMEM_TOTAL (SM_TILES + NSTAGE * STAGE_B)  // 63488 -> 2 CTAs/SM

// ---------------- utility kernels ----------------
__global__ void zero_cnt_kernel() {
    int i = blockIdx.x * blockDim.x + threadIdx.x;
    if (i < N_NODES) g_cnt[i] = 0.f;
}
__global__ void zero_agg_kernel() {
    int i = blockIdx.x * blockDim.x + threadIdx.x;
    if (i < N_NODES * DH / 4)
        ((float4*)g_agg)[i] = make_float4(0.f, 0.f, 0.f, 0.f);
}
__global__ void count_kernel(const int* __restrict__ dstI) {
    int e = blockIdx.x * blockDim.x + threadIdx.x;
    if (e < N_EDGES) atomicAdd(&g_cnt[dstI[e]], 1.f);
}

// fp32 -> fp16 (element pairs)
__global__ void round_f16_kernel(const float* __restrict__ src,
                                 uint16_t* __restrict__ dst, int npairs) {
    int i = blockIdx.x * blockDim.x + threadIdx.x;
    if (i < npairs) {
        float2 v = ((const float2*)src)[i];
        ((uint32_t*)dst)[i] = f16x2(v.x, v.y);
    }
}

// agg: normalize by 1/max(cnt,1), round to fp16
__global__ void norm_agg_kernel() {
    int i = blockIdx.x * blockDim.x + threadIdx.x;
    if (i < N_NODES * DH / 2) {
        int row = i >> 8;  // 256 pairs per row
        float s = 1.f / fmaxf(g_cnt[row], 1.f);
        float2 v = ((const float2*)g_agg)[i];
        ((uint32_t*)g_aggf)[i] = f16x2(v.x * s, v.y * s);
    }
}

// W [K][N] row-major -> Wf [N][K] fp16
__global__ void transpose_f16_kernel(const float* __restrict__ src,
                                     uint16_t* __restrict__ dst,
                                     int K, int N) {
    __shared__ float t[32][33];
    int bx = blockIdx.x * 32, by = blockIdx.y * 32;
    int tx = threadIdx.x, ty = threadIdx.y;
#pragma unroll
    for (int j = 0; j < 32; j += 8) {
        int k = by + ty + j, n = bx + tx;
        t[ty + j][tx] = (k < K && n < N) ? src[(size_t)k * N + n] : 0.f;
    }
    __syncthreads();
#pragma unroll
    for (int j = 0; j < 32; j += 8) {
        int n = bx + ty + j, k = by + tx;
        if (n < N && k < K)
            dst[(size_t)n * K + k] = __half_as_ushort(__float2half_rn(t[tx][ty + j]));
    }
}

// ---------------- fp16 mma.sync mainloop, cp.async 3-stage ring ------------
// 128x128 CTA tile, BK=32, 8 warps (4M x 2N), warp tile 32x64.
template <int KDIM, class AS>
__device__ __forceinline__ void mainloop_mma(
    char* smem, const uint16_t* __restrict__ Wf,
    int n0, AS asrc, float C[2][8][4])
{
    const int tid = threadIdx.x;
    const int lane = tid & 31, warp = tid >> 5;
    const int wm = warp & 3, wn = warp >> 2;
    const uint32_t sb = smem_to_u32(smem);
    constexpr int NC = KDIM / 32;

    auto issue = [&](int c) {
        const int st = c % NSTAGE;
        const uint32_t base = sb + SM_TILES + st * STAGE_B;
#pragma unroll
        for (int halfp = 0; halfp < 2; ++halfp) {
            int id = tid + halfp * 256;
            int row = id >> 2, seg = id & 3;
            int kg = c * 32 + seg * 8;
            uint32_t off = (uint32_t)row * PITCH + seg * 16;
            cp16(base + off, asrc(row, kg));
            cp16(base + TILE_B + off, Wf + (size_t)(n0 + row) * KDIM + kg);
        }
        CP_COMMIT();
    };

    issue(0);
    if (NC > 1) issue(1);
    if (NC > 2) issue(2);

    const int lrow = lane & 15;
    const int lk = (lane >> 4) * 16;

    for (int c = 0; c < NC; ++c) {
        int rem = NC - 1 - c;
        if (rem >= 2) CP_WAIT2(); else if (rem == 1) CP_WAIT1(); else CP_WAIT0();
        __syncthreads();
        const int st = c % NSTAGE;
        const uint32_t sA = sb + SM_TILES + st * STAGE_B;
        const uint32_t sB = sA + TILE_B;
#pragma unroll
        for (int ks = 0; ks < 2; ++ks) {
            uint32_t a[2][4];
#pragma unroll
            for (int i = 0; i < 2; ++i) {
                uint32_t ao = (uint32_t)(32 * wm + 16 * i + lrow) * PITCH + ks * 32 + lk;
                ldsm4(sA + ao, a[i]);
            }
#pragma unroll
            for (int g = 0; g < 4; ++g) {
                uint32_t bo = (uint32_t)(64 * wn + 16 * g + lrow) * PITCH + ks * 32 + lk;
                uint32_t b[4];
                ldsm4(sB + bo, b);
#pragma unroll
                for (int i = 0; i < 2; ++i) {
                    mma_f16(C[i][2 * g],     a[i], b[0], b[2]);
                    mma_f16(C[i][2 * g + 1], a[i], b[1], b[3]);
                }
            }
        }
        __syncthreads();
        if (c + NSTAGE < NC) issue(c + NSTAGE);
    }
}

#define ZERO_C() \
    float C[2][8][4]; \
    _Pragma("unroll") for (int i = 0; i < 2; ++i) \
    _Pragma("unroll") for (int j = 0; j < 8; ++j) \
    _Pragma("unroll") for (int q = 0; q < 4; ++q) C[i][j][q] = 0.f;

// ============================================================================
// GEMM1: m1 = relu([x[dst]|e|x[src]] @ W1a + b1a) -> fp16 m1f
// ============================================================================
__global__ void __launch_bounds__(256, 2) g1_kernel(
    const int* __restrict__ srcI, const int* __restrict__ dstI,
    const uint16_t* __restrict__ Wf, const float* __restrict__ bias)
{
    extern __shared__ char smem[];
    const int tid = threadIdx.x;
    const int n0 = blockIdx.x * 128, m0 = blockIdx.y * 128;
    float* biasS = (float*)(smem + SM_BIAS);
    int* sDst = (int*)(smem + SM_DST);
    int* sSrc = (int*)(smem + SM_SRC);
    if (tid < 128) {
        biasS[tid] = bias[n0 + tid];
        int r = min(m0 + tid, N_EDGES - 1);
        sDst[tid] = dstI[r];
        sSrc[tid] = srcI[r];
    }
    __syncthreads();

    ZERO_C();
    auto asrc = [&](int row, int kg) -> const uint16_t* {
        int r = min(m0 + row, N_EDGES - 1);
        if (kg < DN)      return g_xf + (size_t)sDst[row] * DN + kg;
        if (kg < DN + DE) return g_ef + (size_t)r * DE + (kg - DN);
        return g_xf + (size_t)sSrc[row] * DN + (kg - DN - DE);
    };
    mainloop_mma<2 * DN + DE>(smem, Wf, n0, asrc, C);

    const int lane = tid & 31, warp = tid >> 5;
    const int wm = warp & 3, wn = warp >> 2;
#pragma unroll
    for (int i = 0; i < 2; ++i)
#pragma unroll
    for (int h = 0; h < 2; ++h) {
        int rl = 32 * wm + 16 * i + 8 * h + (lane >> 2);
        int r = m0 + rl;
        if (r >= N_EDGES) continue;
#pragma unroll
        for (int j = 0; j < 8; ++j) {
            int cl = 64 * wn + 8 * j + 2 * (lane & 3);
            float ox = fmaxf(C[i][j][2 * h + 0] + biasS[cl + 0], 0.f);
            float oy = fmaxf(C[i][j][2 * h + 1] + biasS[cl + 1], 0.f);
            ((uint32_t*)g_m1f)[((size_t)r * DH + n0 + cl) >> 1] = f16x2(ox, oy);
        }
    }
}

// ============================================================================
// GEMM2: relu(m1 @ W1b + b1b)   (E x 512)@(512 x 1280)
// cols [0,512)+[768,1280) -> red.v2 into g_agg[dst]; [512,768) -> new_e
// ============================================================================
__global__ void __launch_bounds__(256, 2) g2_kernel(
    const int* __restrict__ dstI,
    const uint16_t* __restrict__ Wf, const float* __restrict__ bias,
    float* __restrict__ eoutF, int last)
{
    extern __shared__ char smem[];
    const int tid = threadIdx.x;
    const int n0 = blockIdx.x * 128, m0 = blockIdx.y * 128;
    float* biasS = (float*)(smem + SM_BIAS);
    int* sDst = (int*)(smem + SM_DST);
    if (tid < 128) {
        biasS[tid] = bias[n0 + tid];
        sDst[tid] = dstI[min(m0 + tid, N_EDGES - 1)];
    }
    __syncthreads();

    ZERO_C();
    auto asrc = [&](int row, int kg) -> const uint16_t* {
        size_t r = (size_t)min(m0 + row, N_EDGES - 1);
        return g_m1f + r * DH + kg;
    };
    mainloop_mma<DH>(smem, Wf, n0, asrc, C);

    const int lane = tid & 31, warp = tid >> 5;
    const int wm = warp & 3, wn = warp >> 2;
    const int mode = (n0 < DH) ? 0 : ((n0 < DH + DE) ? 1 : 2);
    const int aggc0 = (mode == 2) ? (n0 - DH - DE) : n0;
#pragma unroll
    for (int i = 0; i < 2; ++i)
#pragma unroll
    for (int h = 0; h < 2; ++h) {
        int rl = 32 * wm + 16 * i + 8 * h + (lane >> 2);
        int r = m0 + rl;
        if (r >= N_EDGES) continue;
        int dn = sDst[rl];
#pragma unroll
        for (int j = 0; j < 8; ++j) {
            int cl = 64 * wn + 8 * j + 2 * (lane & 3);
            float ox = fmaxf(C[i][j][2 * h + 0] + biasS[cl + 0], 0.f);
            float oy = fmaxf(C[i][j][2 * h + 1] + biasS[cl + 1], 0.f);
            if (mode == 1) {
                size_t eoff = (size_t)r * DE + (n0 - DH) + cl;
                if (last) *(float2*)(eoutF + eoff) = make_float2(ox, oy);
                else      ((uint32_t*)g_ef)[eoff >> 1] = f16x2(ox, oy);
            } else {
                red_add_v2(g_agg + (size_t)dn * DH + aggc0 + cl, ox, oy);
            }
        }
    }
}

// ============================================================================
// GEMM3: h = relu(aggn @ W2a + b2a) -> fp16 hf   (N x 512)@(512 x 512)
// ============================================================================
__global__ void __launch_bounds__(256, 2) g3_kernel(
    const uint16_t* __restrict__ Wf, const float* __restrict__ bias)
{
    extern __shared__ char smem[];
    const int tid = threadIdx.x;
    const int n0 = blockIdx.x * 128, m0 = blockIdx.y * 128;
    float* biasS = (float*)(smem + SM_BIAS);
    if (tid < 128) biasS[tid] = bias[n0 + tid];
    __syncthreads();

    ZERO_C();
    auto asrc = [&](int row, int kg) -> const uint16_t* {
        size_t r = (size_t)min(m0 + row, N_NODES - 1);
        return g_aggf + r * DH + kg;
    };
    mainloop_mma<DH>(smem, Wf, n0, asrc, C);

    const int lane = tid & 31, warp = tid >> 5;
    const int wm = warp & 3, wn = warp >> 2;
#pragma unroll
    for (int i = 0; i < 2; ++i)
#pragma unroll
    for (int h = 0; h < 2; ++h) {
        int rl = 32 * wm + 16 * i + 8 * h + (lane >> 2);
        int r = m0 + rl;
        if (r >= N_NODES) continue;
#pragma unroll
        for (int j = 0; j < 8; ++j) {
            int cl = 64 * wn + 8 * j + 2 * (lane & 3);
            float ox = fmaxf(C[i][j][2 * h + 0] + biasS[cl + 0], 0.f);
            float oy = fmaxf(C[i][j][2 * h + 1] + biasS[cl + 1], 0.f);
            ((uint32_t*)g_hf)[((size_t)r * DH + n0 + cl) >> 1] = f16x2(ox, oy);
        }
    }
}

// ============================================================================
// GEMM4: new_x = x + (h @ W2b + b2b)  [+relu, + fp16 copy for next layer]
// ============================================================================
__global__ void __launch_bounds__(256, 2) g4_kernel(
    const float* __restrict__ xin,
    const uint16_t* __restrict__ Wf, const float* __restrict__ bias,
    float* __restrict__ xoutF, int last)
{
    extern __shared__ char smem[];
    const int tid = threadIdx.x;
    const int n0 = blockIdx.x * 128, m0 = blockIdx.y * 128;
    float* biasS = (float*)(smem + SM_BIAS);
    if (tid < 128) biasS[tid] = bias[n0 + tid];
    __syncthreads();

    ZERO_C();
    auto asrc = [&](int row, int kg) -> const uint16_t* {
        size_t r = (size_t)min(m0 + row, N_NODES - 1);
        return g_hf + r * DH + kg;
    };
    mainloop_mma<DH>(smem, Wf, n0, asrc, C);

    const int lane = tid & 31, warp = tid >> 5;
    const int wm = warp & 3, wn = warp >> 2;
#pragma unroll
    for (int i = 0; i < 2; ++i)
#pragma unroll
    for (int h = 0; h < 2; ++h) {
        int rl = 32 * wm + 16 * i + 8 * h + (lane >> 2);
        int r = m0 + rl;
        if (r >= N_NODES) continue;
        const float* xrow = xin + (size_t)r * DN + n0;
#pragma unroll
        for (int j = 0; j < 8; ++j) {
            int cl = 64 * wn + 8 * j + 2 * (lane & 3);
            float2 xv = *(const float2*)(xrow + cl);
            float ox = C[i][j][2 * h + 0] + biasS[cl + 0] + xv.x;
            float oy = C[i][j][2 * h + 1] + biasS[cl + 1] + xv.y;
            size_t xoff = (size_t)r * DN + n0 + cl;
            if (last) {
                *(float2*)(xoutF + xoff) = make_float2(ox, oy);
            } else {
                ox = fmaxf(ox, 0.f); oy = fmaxf(oy, 0.f);
                *(float2*)(xoutF + xoff) = make_float2(ox, oy);
                ((uint32_t*)g_xf)[xoff >> 1] = f16x2(ox, oy);
            }
        }
    }
}

// ============================================================================
extern "C" void kernel_launch(void* const* d_in, const int* in_sizes, int n_in,
                              void* d_out, int out_size)
{
    (void)in_sizes; (void)n_in; (void)out_size;
    const float* node = (const float*)d_in[0];
    const float* edge = (const float*)d_in[1];
    const int*   eidx = (const int*)  d_in[2];
    const float* W1a  = (const float*)d_in[3];
    const float* b1a  = (const float*)d_in[4];
    const float* W1b  = (const float*)d_in[5];
    const float* b1b  = (const float*)d_in[6];
    const float* W2a  = (const float*)d_in[7];
    const float* b2a  = (const float*)d_in[8];
    const float* W2b  = (const float*)d_in[9];
    const float* b2b  = (const float*)d_in[10];
    float* out = (float*)d_out;

    const int* srcI = eidx;
    const int* dstI = eidx + N_EDGES;

    cudaFuncSetAttribute(g1_kernel, cudaFuncAttributeMaxDynamicSharedMemorySize, SMEM_TOTAL);
    cudaFuncSetAttribute(g2_kernel, cudaFuncAttributeMaxDynamicSharedMemorySize, SMEM_TOTAL);
    cudaFuncSetAttribute(g3_kernel, cudaFuncAttributeMaxDynamicSharedMemorySize, SMEM_TOTAL);
    cudaFuncSetAttribute(g4_kernel, cudaFuncAttributeMaxDynamicSharedMemorySize, SMEM_TOTAL);

    void* t;
    cudaGetSymbolAddress(&t, g_x);  float* p_gx = (float*)t;
    cudaGetSymbolAddress(&t, g_xf); uint16_t* p_xf = (uint16_t*)t;
    cudaGetSymbolAddress(&t, g_ef); uint16_t* p_ef = (uint16_t*)t;
    cudaGetSymbolAddress(&t, g_Wf); uint16_t* p_wf = (uint16_t*)t;

    // one-time rounding of the inputs to fp16
    {
        int np = N_NODES * DN / 2;
        round_f16_kernel<<<(np + 255) / 256, 256>>>(node, p_xf, np);
        np = N_EDGES * DE / 2;
        round_f16_kernel<<<(np + 255) / 256, 256>>>(edge, p_ef, np);
    }

    // pre-transpose all weights to [N][K] fp16
    dim3 tb(32, 8);
    for (int l = 0; l < NLAYERS; ++l) {
        size_t base = (size_t)l * WT_LAYER;
        transpose_f16_kernel<<<dim3(DH / 32, (2 * DN + DE) / 32), tb>>>(
            W1a + (size_t)l * (2 * DN + DE) * DH, p_wf + base + OFF_W1A,
            2 * DN + DE, DH);
        transpose_f16_kernel<<<dim3((2 * DH + DE) / 32, DH / 32), tb>>>(
            W1b + (size_t)l * DH * (2 * DH + DE), p_wf + base + OFF_W1B,
            DH, 2 * DH + DE);
        transpose_f16_kernel<<<dim3(DH / 32, DH / 32), tb>>>(
            W2a + (size_t)l * DH * DH, p_wf + base + OFF_W2A, DH, DH);
        transpose_f16_kernel<<<dim3(DN / 32, DH / 32), tb>>>(
            W2b + (size_t)l * DH * DN, p_wf + base + OFF_W2B, DH, DN);
    }

    zero_cnt_kernel<<<(N_NODES + 255) / 256, 256>>>();
    count_kernel<<<(N_EDGES + 255) / 256, 256>>>(dstI);

    const int MT_E = (N_EDGES + 127) / 128;  // 782
    const int MT_N = (N_NODES + 127) / 128;  // 157

    for (int l = 0; l < NLAYERS; ++l) {
        const int last = (l == NLAYERS - 1) ? 1 : 0;
        size_t base = (size_t)l * WT_LAYER;

        zero_agg_kernel<<<(N_NODES * DH / 4 + 255) / 256, 256>>>();

        g1_kernel<<<dim3(DH / 128, MT_E), 256, SMEM_TOTAL>>>(
            srcI, dstI, p_wf + base + OFF_W1A, b1a + (size_t)l * DH);

        g2_kernel<<<dim3((2 * DH + DE) / 128, MT_E), 256, SMEM_TOTAL>>>(
            dstI, p_wf + base + OFF_W1B, b1b + (size_t)l * (2 * DH + DE),
            last ? (out + (size_t)N_NODES * DN) : nullptr, last);

        norm_agg_kernel<<<(N_NODES * DH / 2 + 255) / 256, 256>>>();

        g3_kernel<<<dim3(DH / 128, MT_N), 256, SMEM_TOTAL>>>(
            p_wf + base + OFF_W2A, b2a + (size_t)l * DH);

        const float* xin = (l == 0) ? node : p_gx;
        g4_kernel<<<dim3(DN / 128, MT_N), 256, SMEM_TOTAL>>>(
            xin, p_wf + base + OFF_W2B, b2b + (size_t)l * DN,
            last ? out : p_gx, last);
    }
}